// round 11
// baseline (speedup 1.0000x reference)
#include <cuda_runtime.h>
#include <cuda_fp16.h>
#include <math.h>
#include <stdint.h>

#define HH 96
#define WW 96
#define HWc 9216         // 96*96
#define BB 4
#define NN 36864         // BB*HWc

// ---------------- scratch (static device arrays; no cudaMalloc) --------------
__device__ uint16_t g_col[169869312];    // f16: [NN][K] K-major (K<=4608), 340MB
__device__ uint16_t g_wAh[1179648];      // f16 hi: [Opad][K] K-major
__device__ uint16_t g_wAl[1179648];      // f16 lo
__device__ float    g_y1[2359296];       // 4*64*9216
__device__ float    g_y2[18874368];      // 4*512*9216
__device__ float    g_py[331776];        // 4*9*9216
__device__ float    g_px[331776];
__device__ float    g_mask[331776];

// ---------------- PTX helpers (generic compute_103-legal only) ---------------
__device__ __forceinline__ uint32_t smem_u32(const void* p) {
    uint32_t a;
    asm("{ .reg .u64 t; cvta.to.shared.u64 t, %1; cvt.u32.u64 %0, t; }"
        : "=r"(a) : "l"(p));
    return a;
}

__device__ __forceinline__ void cp16(uint32_t saddr, const void* g) {
    asm volatile("cp.async.cg.shared.global [%0], [%1], 16;"
                 :: "r"(saddr), "l"(g) : "memory");
}

__device__ __forceinline__ void cp_commit() {
    asm volatile("cp.async.commit_group;" ::: "memory");
}

template<int N>
__device__ __forceinline__ void cp_wait() {
    asm volatile("cp.async.wait_group %0;" :: "n"(N) : "memory");
}

__device__ __forceinline__ void ldsm4(uint32_t* r, uint32_t addr) {
    asm volatile("ldmatrix.sync.aligned.m8n8.x4.shared.b16 {%0,%1,%2,%3}, [%4];"
                 : "=r"(r[0]), "=r"(r[1]), "=r"(r[2]), "=r"(r[3]) : "r"(addr));
}

__device__ __forceinline__ void mma_f16(float* d, const uint32_t* a,
                                        const uint32_t* b) {
    asm volatile(
        "mma.sync.aligned.m16n8k16.row.col.f32.f16.f16.f32 "
        "{%0,%1,%2,%3}, {%4,%5,%6,%7}, {%8,%9}, {%0,%1,%2,%3};"
        : "+f"(d[0]), "+f"(d[1]), "+f"(d[2]), "+f"(d[3])
        : "r"(a[0]), "r"(a[1]), "r"(a[2]), "r"(a[3]), "r"(b[0]), "r"(b[1]));
}

// ---------------- 1) offset conv: om = conv3x3(x, ow) + ob -> py/px/mask -----
template<int CB>
__global__ void offset_conv_kernel(const float* __restrict__ x,
                                   const float* __restrict__ ow,
                                   const float* __restrict__ ob, int C)
{
    __shared__ float ws[CB * 9 * 28];
    const int tid = threadIdx.x;
    const int tx = tid & 31, ty = tid >> 5;
    const int w0 = blockIdx.x * 32 + tx;
    const int h0 = blockIdx.y * 8 + ty;
    const int b  = blockIdx.z;

    float acc[28];
#pragma unroll
    for (int i = 0; i < 28; i++) acc[i] = 0.f;

    for (int c0 = 0; c0 < C; c0 += CB) {
        __syncthreads();
        for (int i = tid; i < CB * 9 * 28; i += 256) {
            int oc  = i % 28;
            int r   = i / 28;
            int tap = r % 9;
            int cc  = r / 9;
            ws[i] = (oc < 27) ? ow[((size_t)oc * C + c0 + cc) * 9 + tap] : 0.f;
        }
        __syncthreads();

        for (int cc = 0; cc < CB; cc++) {
            const float* xp = x + ((size_t)b * C + c0 + cc) * HWc;
            float xv[9];
#pragma unroll
            for (int dy = 0; dy < 3; dy++)
#pragma unroll
                for (int dx = 0; dx < 3; dx++) {
                    int yy = h0 + dy - 1, xx = w0 + dx - 1;
                    bool v = (yy >= 0) & (yy < HH) & (xx >= 0) & (xx < WW);
                    xv[dy * 3 + dx] = v ? xp[yy * WW + xx] : 0.f;
                }
#pragma unroll
            for (int tap = 0; tap < 9; tap++) {
                const float* wr = &ws[(cc * 9 + tap) * 28];
                float xvv = xv[tap];
#pragma unroll
                for (int q = 0; q < 7; q++) {
                    float4 wv = *(const float4*)(wr + q * 4);
                    acc[q * 4 + 0] += xvv * wv.x;
                    acc[q * 4 + 1] += xvv * wv.y;
                    acc[q * 4 + 2] += xvv * wv.z;
                    acc[q * 4 + 3] += xvv * wv.w;
                }
            }
        }
    }

#pragma unroll
    for (int i = 0; i < 27; i++) acc[i] += ob[i];

    const int pix = h0 * WW + w0;
#pragma unroll
    for (int k = 0; k < 9; k++) {
        float oy = acc[2 * k];
        float ox = acc[2 * k + 1];
        float m  = 1.f / (1.f + __expf(-acc[18 + k]));
        int ky = k / 3, kx = k % 3;
        int idx = (b * 9 + k) * HWc + pix;
        g_py[idx]   = (float)(h0 + ky - 1) + oy;
        g_px[idx]   = (float)(w0 + kx - 1) + ox;
        g_mask[idx] = m;
    }
}

// ---------------- 2) deformable im2col gather -> g_col (f16, [N][K]) ---------
__global__ void gather_kernel(const float* __restrict__ x, int C)
{
    int idx = blockIdx.x * blockDim.x + threadIdx.x;  // over BB*9*HWc
    if (idx >= BB * 9 * HWc) return;
    int hw = idx % HWc;
    int bk = idx / HWc;
    int k  = bk % 9;
    int b  = bk / 9;
    const int K = 9 * C;
    const size_t n = (size_t)b * HWc + hw;

    float pyv = g_py[idx], pxv = g_px[idx], m = g_mask[idx];
    float y0f = floorf(pyv), x0f = floorf(pxv);
    float wy = pyv - y0f, wx = pxv - x0f;
    int y0 = (int)y0f, x0 = (int)x0f;
    int y1 = y0 + 1, x1 = x0 + 1;
    float vy0 = (y0 >= 0 && y0 < HH) ? 1.f : 0.f;
    float vy1 = (y1 >= 0 && y1 < HH) ? 1.f : 0.f;
    float vx0 = (x0 >= 0 && x0 < WW) ? 1.f : 0.f;
    float vx1 = (x1 >= 0 && x1 < WW) ? 1.f : 0.f;
    float w00 = (1.f - wy) * (1.f - wx) * m * vy0 * vx0;
    float w01 = (1.f - wy) * wx         * m * vy0 * vx1;
    float w10 = wy         * (1.f - wx) * m * vy1 * vx0;
    float w11 = wy         * wx         * m * vy1 * vx1;

    int cy0 = min(max(y0, 0), HH - 1), cy1 = min(max(y1, 0), HH - 1);
    int cx0 = min(max(x0, 0), WW - 1), cx1 = min(max(x1, 0), WW - 1);
    int o00 = cy0 * WW + cx0, o01 = cy0 * WW + cx1;
    int o10 = cy1 * WW + cx0, o11 = cy1 * WW + cx1;

    const float* base = x + (size_t)b * C * HWc;
    size_t outBase = n * (size_t)K + (size_t)k * C;

    for (int c = 0; c < C; c += 4) {
        uint16_t h[4];
#pragma unroll
        for (int j = 0; j < 4; j++) {
            const float* p = base + (size_t)(c + j) * HWc;
            float v = w00 * p[o00] + w01 * p[o01] + w10 * p[o10] + w11 * p[o11];
            h[j] = __half_as_ushort(__float2half_rn(v));
        }
        uint2 pk;
        pk.x = (uint32_t)h[0] | ((uint32_t)h[1] << 16);
        pk.y = (uint32_t)h[2] | ((uint32_t)h[3] << 16);
        *reinterpret_cast<uint2*>(&g_col[outBase + c]) = pk;
    }
}

// ---------------- 3a) weight repack+split: wA[o][tap*C+c] = w[o][c][tap] -----
__global__ void repack_split_kernel(const float* __restrict__ w,
                                    int O, int Opad, int C)
{
    int K = 9 * C;
    int idx = blockIdx.x * blockDim.x + threadIdx.x;
    if (idx >= Opad * K) return;
    int kk = idx % K;
    int o  = idx / K;
    int tap = kk / C;
    int c   = kk % C;
    float v = (o < O) ? w[((size_t)o * C + c) * 9 + tap] : 0.f;
    __half h = __float2half_rn(v);
    __half l = __float2half_rn(v - __half2float(h));
    g_wAh[idx] = __half_as_ushort(h);
    g_wAl[idx] = __half_as_ushort(l);
}

// ---------------- 3b) fp16 A-split HMMA GEMM, 3-stage pipeline ---------------
// D[O,N] = (Ah+Al)·col^T, 2 MMA passes.  CTA 128x128, 8 warps (4M x 2N),
// warp tile 32x64.  KC=64 (128B rows), RS=144 (conflict-free ldmatrix).
// 3-stage cp.async circular buffer, ONE __syncthreads per K-chunk.
#define KC 64
#define RS 144
#define ASZ (128 * RS)           // one tile (Ah | Al | B), 18432 B
#define STG (3 * ASZ)            // stage = 55296 B
#define GSMEM_TOTAL (3 * STG)    // 165888 B

__global__ void __launch_bounds__(256)
dcn_gemm_kernel(const float* __restrict__ bias, float* __restrict__ out,
                int K, int O)
{
    extern __shared__ char smem[];
    const uint32_t sb = smem_u32(smem);
    const int tid = threadIdx.x, lid = tid & 31, wid = tid >> 5;
    const int warpM = wid & 3;        // 0..3 -> 32-row slices
    const int warpN = wid >> 2;       // 0..1 -> 64-col slices
    const int m0 = blockIdx.y * 128;
    const int n0 = blockIdx.x * 128;

    float acc[2][8][4];
#pragma unroll
    for (int mt = 0; mt < 2; mt++)
#pragma unroll
        for (int nt = 0; nt < 8; nt++)
#pragma unroll
            for (int r = 0; r < 4; r++) acc[mt][nt][r] = 0.f;

    const char* pAh = (const char*)g_wAh + (size_t)m0 * K * 2;
    const char* pAl = (const char*)g_wAl + (size_t)m0 * K * 2;
    const char* pB  = (const char*)g_col + (size_t)n0 * K * 2;

    auto load_chunk = [&](int c, int buf) {
        size_t kb = (size_t)c * (KC * 2);
        uint32_t sbase = sb + (uint32_t)buf * STG;
        // 384 rows x 8 x 16B segments, 256 threads -> 12 cp.async each
#pragma unroll
        for (int i = 0; i < 12; i++) {
            int s   = tid + i * 256;
            int row = s >> 3;
            int seg = s & 7;
            const char* g;
            uint32_t so;
            if (row < 128) {
                g  = pAh + (size_t)row * K * 2 + kb + (size_t)seg * 16;
                so = sbase + row * RS + seg * 16;
            } else if (row < 256) {
                int r = row - 128;
                g  = pAl + (size_t)r * K * 2 + kb + (size_t)seg * 16;
                so = sbase + ASZ + r * RS + seg * 16;
            } else {
                int r = row - 256;
                g  = pB + (size_t)r * K * 2 + kb + (size_t)seg * 16;
                so = sbase + 2 * ASZ + r * RS + seg * 16;
            }
            cp16(so, g);
        }
    };

    auto compute_chunk = [&](int buf) {
        uint32_t base = sb + (uint32_t)buf * STG;
        const uint32_t lrow = lid & 15;
        const uint32_t lcol = (lid >> 4) * 16;
#pragma unroll
        for (int ks = 0; ks < 4; ks++) {
            const uint32_t kb = ks * 32;
            uint32_t bb[8][2];
#pragma unroll
            for (int np = 0; np < 4; np++) {
                uint32_t t[4];
                uint32_t r = warpN * 64 + np * 16 + lrow;
                ldsm4(t, base + 2 * ASZ + r * RS + kb + lcol);
                bb[2 * np][0] = t[0]; bb[2 * np][1] = t[2];
                bb[2 * np + 1][0] = t[1]; bb[2 * np + 1][1] = t[3];
            }
            uint32_t af[2][4];
#pragma unroll
            for (int mt = 0; mt < 2; mt++) {
                uint32_t r = warpM * 32 + mt * 16 + lrow;
                ldsm4(af[mt], base + r * RS + kb + lcol);
            }
#pragma unroll
            for (int mt = 0; mt < 2; mt++)
#pragma unroll
                for (int nt = 0; nt < 8; nt++)
                    mma_f16(acc[mt][nt], af[mt], bb[nt]);      // Ah*B
#pragma unroll
            for (int mt = 0; mt < 2; mt++) {
                uint32_t r = warpM * 32 + mt * 16 + lrow;
                ldsm4(af[mt], base + ASZ + r * RS + kb + lcol);
            }
#pragma unroll
            for (int mt = 0; mt < 2; mt++)
#pragma unroll
                for (int nt = 0; nt < 8; nt++)
                    mma_f16(acc[mt][nt], af[mt], bb[nt]);      // Al*B
        }
    };

    const int nCh = K / KC;   // >= 9 always

    load_chunk(0, 0); cp_commit();
    load_chunk(1, 1); cp_commit();

    int buf = 0;
    for (int c = 0; c < nCh; c++) {
        if (c + 1 < nCh) cp_wait<1>(); else cp_wait<0>();   // chunk c arrived
        __syncthreads();   // also retires compute(c-1) -> buffer (c+2)%3 free
        if (c + 2 < nCh) {
            int nb = buf + 2; if (nb >= 3) nb -= 3;
            load_chunk(c + 2, nb);
            cp_commit();
        }
        compute_chunk(buf);
        if (++buf == 3) buf = 0;
    }

    // ---- epilogue: +bias, scatter into [B, O, H, W] -------------------------
    const int b   = n0 / HWc;
    const int hw0 = n0 % HWc;
    const int grp = lid >> 2;
    const int tig = lid & 3;
#pragma unroll
    for (int mt = 0; mt < 2; mt++) {
        int oA = m0 + warpM * 32 + mt * 16 + grp;
        int oB = oA + 8;
#pragma unroll
        for (int nt = 0; nt < 8; nt++) {
            int cn = warpN * 64 + nt * 8 + tig * 2;
            if (oA < O) {
                float bv = bias[oA];
                float2 v = make_float2(acc[mt][nt][0] + bv, acc[mt][nt][1] + bv);
                *(float2*)(out + ((size_t)b * O + oA) * HWc + hw0 + cn) = v;
            }
            if (oB < O) {
                float bv = bias[oB];
                float2 v = make_float2(acc[mt][nt][2] + bv, acc[mt][nt][3] + bv);
                *(float2*)(out + ((size_t)b * O + oB) * HWc + hw0 + cn) = v;
            }
        }
    }
}

// ---------------- host-side layer driver -------------------------------------
static void run_layer(const float* in, int C,
                      const float* ow, const float* obias,
                      const float* w, const float* bias,
                      int O, int Opad, float* out)
{
    dim3 gOff(WW / 32, HH / 8, BB);
    offset_conv_kernel<16><<<gOff, 256>>>(in, ow, obias, C);

    int nG = BB * 9 * HWc;
    gather_kernel<<<(nG + 255) / 256, 256>>>(in, C);

    int K = 9 * C;
    int nW = Opad * K;
    repack_split_kernel<<<(nW + 255) / 256, 256>>>(w, O, Opad, C);

    dim3 grid(NN / 128, Opad / 128);
    dcn_gemm_kernel<<<grid, 256, GSMEM_TOTAL>>>(bias, out, K, O);
}

extern "C" void kernel_launch(void* const* d_in, const int* in_sizes, int n_in,
                              void* d_out, int out_size)
{
    const float* x   = (const float*)d_in[0];
    const float* ow1 = (const float*)d_in[1];
    const float* ob1 = (const float*)d_in[2];
    const float* w1  = (const float*)d_in[3];
    const float* b1  = (const float*)d_in[4];
    const float* ow2 = (const float*)d_in[5];
    const float* ob2 = (const float*)d_in[6];
    const float* w2  = (const float*)d_in[7];
    const float* b2  = (const float*)d_in[8];
    const float* ow3 = (const float*)d_in[9];
    const float* ob3 = (const float*)d_in[10];
    const float* w3  = (const float*)d_in[11];
    const float* b3  = (const float*)d_in[12];
    float* out = (float*)d_out;

    cudaFuncSetAttribute(dcn_gemm_kernel,
                         cudaFuncAttributeMaxDynamicSharedMemorySize, GSMEM_TOTAL);

    float *y1 = nullptr, *y2 = nullptr;
    cudaGetSymbolAddress((void**)&y1, g_y1);
    cudaGetSymbolAddress((void**)&y2, g_y2);

    run_layer(x,   64, ow1, ob1, w1, b1,  64, 128, y1);
    run_layer(y1,  64, ow2, ob2, w2, b2, 512, 512, y2);
    run_layer(y2, 512, ow3, ob3, w3, b3, 256, 256, out);
}

// round 12
// speedup vs baseline: 1.2368x; 1.2368x over previous
#include <cuda_runtime.h>
#include <cuda_fp16.h>
#include <math.h>
#include <stdint.h>

#define HH 96
#define WW 96
#define HWc 9216         // 96*96
#define BB 4
#define NN 36864         // BB*HWc

// ---------------- scratch (static device arrays; no cudaMalloc) --------------
__device__ uint16_t g_col[169869312];    // f16: [NN][K] K-major (K<=4608), 340MB
__device__ uint16_t g_wA[1179648];       // f16: [Opad][K] K-major
__device__ float    g_y1[2359296];       // 4*64*9216
__device__ float    g_y2[18874368];      // 4*512*9216
__device__ float    g_py[331776];        // 4*9*9216
__device__ float    g_px[331776];
__device__ float    g_mask[331776];

// ---------------- PTX helpers (generic compute_103-legal only) ---------------
__device__ __forceinline__ uint32_t smem_u32(const void* p) {
    uint32_t a;
    asm("{ .reg .u64 t; cvta.to.shared.u64 t, %1; cvt.u32.u64 %0, t; }"
        : "=r"(a) : "l"(p));
    return a;
}

__device__ __forceinline__ void cp16(uint32_t saddr, const void* g) {
    asm volatile("cp.async.cg.shared.global [%0], [%1], 16;"
                 :: "r"(saddr), "l"(g) : "memory");
}

__device__ __forceinline__ void cp_commit() {
    asm volatile("cp.async.commit_group;" ::: "memory");
}

template<int N>
__device__ __forceinline__ void cp_wait() {
    asm volatile("cp.async.wait_group %0;" :: "n"(N) : "memory");
}

__device__ __forceinline__ void ldsm4(uint32_t* r, uint32_t addr) {
    asm volatile("ldmatrix.sync.aligned.m8n8.x4.shared.b16 {%0,%1,%2,%3}, [%4];"
                 : "=r"(r[0]), "=r"(r[1]), "=r"(r[2]), "=r"(r[3]) : "r"(addr));
}

__device__ __forceinline__ void mma_f16(float* d, const uint32_t* a,
                                        const uint32_t* b) {
    asm volatile(
        "mma.sync.aligned.m16n8k16.row.col.f32.f16.f16.f32 "
        "{%0,%1,%2,%3}, {%4,%5,%6,%7}, {%8,%9}, {%0,%1,%2,%3};"
        : "+f"(d[0]), "+f"(d[1]), "+f"(d[2]), "+f"(d[3])
        : "r"(a[0]), "r"(a[1]), "r"(a[2]), "r"(a[3]), "r"(b[0]), "r"(b[1]));
}

// ---------------- 1) offset conv: om = conv3x3(x, ow) + ob -> py/px/mask -----
template<int CB>
__global__ void offset_conv_kernel(const float* __restrict__ x,
                                   const float* __restrict__ ow,
                                   const float* __restrict__ ob, int C)
{
    __shared__ float ws[CB * 9 * 28];
    const int tid = threadIdx.x;
    const int tx = tid & 31, ty = tid >> 5;
    const int w0 = blockIdx.x * 32 + tx;
    const int h0 = blockIdx.y * 8 + ty;
    const int b  = blockIdx.z;

    float acc[28];
#pragma unroll
    for (int i = 0; i < 28; i++) acc[i] = 0.f;

    for (int c0 = 0; c0 < C; c0 += CB) {
        __syncthreads();
        for (int i = tid; i < CB * 9 * 28; i += 256) {
            int oc  = i % 28;
            int r   = i / 28;
            int tap = r % 9;
            int cc  = r / 9;
            ws[i] = (oc < 27) ? ow[((size_t)oc * C + c0 + cc) * 9 + tap] : 0.f;
        }
        __syncthreads();

        for (int cc = 0; cc < CB; cc++) {
            const float* xp = x + ((size_t)b * C + c0 + cc) * HWc;
            float xv[9];
#pragma unroll
            for (int dy = 0; dy < 3; dy++)
#pragma unroll
                for (int dx = 0; dx < 3; dx++) {
                    int yy = h0 + dy - 1, xx = w0 + dx - 1;
                    bool v = (yy >= 0) & (yy < HH) & (xx >= 0) & (xx < WW);
                    xv[dy * 3 + dx] = v ? xp[yy * WW + xx] : 0.f;
                }
#pragma unroll
            for (int tap = 0; tap < 9; tap++) {
                const float* wr = &ws[(cc * 9 + tap) * 28];
                float xvv = xv[tap];
#pragma unroll
                for (int q = 0; q < 7; q++) {
                    float4 wv = *(const float4*)(wr + q * 4);
                    acc[q * 4 + 0] += xvv * wv.x;
                    acc[q * 4 + 1] += xvv * wv.y;
                    acc[q * 4 + 2] += xvv * wv.z;
                    acc[q * 4 + 3] += xvv * wv.w;
                }
            }
        }
    }

#pragma unroll
    for (int i = 0; i < 27; i++) acc[i] += ob[i];

    const int pix = h0 * WW + w0;
#pragma unroll
    for (int k = 0; k < 9; k++) {
        float oy = acc[2 * k];
        float ox = acc[2 * k + 1];
        float m  = 1.f / (1.f + __expf(-acc[18 + k]));
        int ky = k / 3, kx = k % 3;
        int idx = (b * 9 + k) * HWc + pix;
        g_py[idx]   = (float)(h0 + ky - 1) + oy;
        g_px[idx]   = (float)(w0 + kx - 1) + ox;
        g_mask[idx] = m;
    }
}

// ---------------- 2) deformable im2col gather -> g_col (f16, [N][K]) ---------
__global__ void gather_kernel(const float* __restrict__ x, int C)
{
    int idx = blockIdx.x * blockDim.x + threadIdx.x;  // over BB*9*HWc
    if (idx >= BB * 9 * HWc) return;
    int hw = idx % HWc;
    int bk = idx / HWc;
    int k  = bk % 9;
    int b  = bk / 9;
    const int K = 9 * C;
    const size_t n = (size_t)b * HWc + hw;

    float pyv = g_py[idx], pxv = g_px[idx], m = g_mask[idx];
    float y0f = floorf(pyv), x0f = floorf(pxv);
    float wy = pyv - y0f, wx = pxv - x0f;
    int y0 = (int)y0f, x0 = (int)x0f;
    int y1 = y0 + 1, x1 = x0 + 1;
    float vy0 = (y0 >= 0 && y0 < HH) ? 1.f : 0.f;
    float vy1 = (y1 >= 0 && y1 < HH) ? 1.f : 0.f;
    float vx0 = (x0 >= 0 && x0 < WW) ? 1.f : 0.f;
    float vx1 = (x1 >= 0 && x1 < WW) ? 1.f : 0.f;
    float w00 = (1.f - wy) * (1.f - wx) * m * vy0 * vx0;
    float w01 = (1.f - wy) * wx         * m * vy0 * vx1;
    float w10 = wy         * (1.f - wx) * m * vy1 * vx0;
    float w11 = wy         * wx         * m * vy1 * vx1;

    int cy0 = min(max(y0, 0), HH - 1), cy1 = min(max(y1, 0), HH - 1);
    int cx0 = min(max(x0, 0), WW - 1), cx1 = min(max(x1, 0), WW - 1);
    int o00 = cy0 * WW + cx0, o01 = cy0 * WW + cx1;
    int o10 = cy1 * WW + cx0, o11 = cy1 * WW + cx1;

    const float* base = x + (size_t)b * C * HWc;
    size_t outBase = n * (size_t)K + (size_t)k * C;

    for (int c = 0; c < C; c += 4) {
        uint16_t h[4];
#pragma unroll
        for (int j = 0; j < 4; j++) {
            const float* p = base + (size_t)(c + j) * HWc;
            float v = w00 * p[o00] + w01 * p[o01] + w10 * p[o10] + w11 * p[o11];
            h[j] = __half_as_ushort(__float2half_rn(v));
        }
        uint2 pk;
        pk.x = (uint32_t)h[0] | ((uint32_t)h[1] << 16);
        pk.y = (uint32_t)h[2] | ((uint32_t)h[3] << 16);
        *reinterpret_cast<uint2*>(&g_col[outBase + c]) = pk;
    }
}

// ---------------- 3a) weight repack: wA[o][tap*C+c] = f16(w[o][c][tap]) ------
__global__ void repack_kernel(const float* __restrict__ w,
                              int O, int Opad, int C)
{
    int K = 9 * C;
    int idx = blockIdx.x * blockDim.x + threadIdx.x;
    if (idx >= Opad * K) return;
    int kk = idx % K;
    int o  = idx / K;
    int tap = kk / C;
    int c   = kk % C;
    float v = (o < O) ? w[((size_t)o * C + c) * 9 + tap] : 0.f;
    g_wA[idx] = __half_as_ushort(__float2half_rn(v));
}

// ---------------- 3b) fp16 HMMA GEMM, 2-stage, 2 CTAs/SM ---------------------
// D[O,N] = wA · col^T.  CTA 128x128, 8 warps (4M x 2N), warp tile 32x64.
// KC=64 (128B rows), RS=144 padded stride (conflict-free ldmatrix).
// Single fp16 pass; 2-stage cp.async; launch_bounds(256,2) -> 2 CTAs/SM.
#define KC 64
#define RS 144
#define ASZ (128 * RS)           // one tile (A or B), 18432 B
#define STG (2 * ASZ)            // stage = 36864 B
#define GSMEM_TOTAL (2 * STG)    // 73728 B -> 2 CTAs/SM

__global__ void __launch_bounds__(256, 2)
dcn_gemm_kernel(const float* __restrict__ bias, float* __restrict__ out,
                int K, int O)
{
    extern __shared__ char smem[];
    const uint32_t sb = smem_u32(smem);
    const int tid = threadIdx.x, lid = tid & 31, wid = tid >> 5;
    const int warpM = wid & 3;        // 0..3 -> 32-row slices
    const int warpN = wid >> 2;       // 0..1 -> 64-col slices
    const int m0 = blockIdx.y * 128;
    const int n0 = blockIdx.x * 128;

    float acc[2][8][4];
#pragma unroll
    for (int mt = 0; mt < 2; mt++)
#pragma unroll
        for (int nt = 0; nt < 8; nt++)
#pragma unroll
            for (int r = 0; r < 4; r++) acc[mt][nt][r] = 0.f;

    const char* pA = (const char*)g_wA  + (size_t)m0 * K * 2;
    const char* pB = (const char*)g_col + (size_t)n0 * K * 2;

    auto load_chunk = [&](int c, int buf) {
        size_t kb = (size_t)c * (KC * 2);
        uint32_t sbase = sb + (uint32_t)buf * STG;
        // 256 rows x 8 x 16B segments, 256 threads -> 8 cp.async each
#pragma unroll
        for (int i = 0; i < 8; i++) {
            int s   = tid + i * 256;
            int row = s >> 3;
            int seg = s & 7;
            const char* g;
            uint32_t so;
            if (row < 128) {
                g  = pA + (size_t)row * K * 2 + kb + (size_t)seg * 16;
                so = sbase + row * RS + seg * 16;
            } else {
                int r = row - 128;
                g  = pB + (size_t)r * K * 2 + kb + (size_t)seg * 16;
                so = sbase + ASZ + r * RS + seg * 16;
            }
            cp16(so, g);
        }
    };

    auto compute_chunk = [&](int buf) {
        uint32_t base = sb + (uint32_t)buf * STG;
        const uint32_t lrow = lid & 15;
        const uint32_t lcol = (lid >> 4) * 16;
#pragma unroll
        for (int ks = 0; ks < 4; ks++) {
            const uint32_t kb = ks * 32;
            uint32_t bb[8][2];
#pragma unroll
            for (int np = 0; np < 4; np++) {
                uint32_t t[4];
                uint32_t r = warpN * 64 + np * 16 + lrow;
                ldsm4(t, base + ASZ + r * RS + kb + lcol);
                bb[2 * np][0] = t[0]; bb[2 * np][1] = t[2];
                bb[2 * np + 1][0] = t[1]; bb[2 * np + 1][1] = t[3];
            }
            uint32_t af[2][4];
#pragma unroll
            for (int mt = 0; mt < 2; mt++) {
                uint32_t r = warpM * 32 + mt * 16 + lrow;
                ldsm4(af[mt], base + r * RS + kb + lcol);
            }
#pragma unroll
            for (int mt = 0; mt < 2; mt++)
#pragma unroll
                for (int nt = 0; nt < 8; nt++)
                    mma_f16(acc[mt][nt], af[mt], bb[nt]);
        }
    };

    const int nCh = K / KC;   // >= 9 always

    load_chunk(0, 0);
    cp_commit();

    for (int c = 0; c < nCh; c++) {
        int buf = c & 1;
        if (c + 1 < nCh) {
            load_chunk(c + 1, buf ^ 1);
            cp_commit();
            cp_wait<1>();
        } else {
            cp_wait<0>();
        }
        __syncthreads();
        compute_chunk(buf);
        __syncthreads();
    }

    // ---- epilogue: +bias, scatter into [B, O, H, W] -------------------------
    const int b   = n0 / HWc;
    const int hw0 = n0 % HWc;
    const int grp = lid >> 2;
    const int tig = lid & 3;
#pragma unroll
    for (int mt = 0; mt < 2; mt++) {
        int oA = m0 + warpM * 32 + mt * 16 + grp;
        int oB = oA + 8;
#pragma unroll
        for (int nt = 0; nt < 8; nt++) {
            int cn = warpN * 64 + nt * 8 + tig * 2;
            if (oA < O) {
                float bv = bias[oA];
                float2 v = make_float2(acc[mt][nt][0] + bv, acc[mt][nt][1] + bv);
                *(float2*)(out + ((size_t)b * O + oA) * HWc + hw0 + cn) = v;
            }
            if (oB < O) {
                float bv = bias[oB];
                float2 v = make_float2(acc[mt][nt][2] + bv, acc[mt][nt][3] + bv);
                *(float2*)(out + ((size_t)b * O + oB) * HWc + hw0 + cn) = v;
            }
        }
    }
}

// ---------------- host-side layer driver -------------------------------------
static void run_layer(const float* in, int C,
                      const float* ow, const float* obias,
                      const float* w, const float* bias,
                      int O, int Opad, float* out)
{
    dim3 gOff(WW / 32, HH / 8, BB);
    offset_conv_kernel<16><<<gOff, 256>>>(in, ow, obias, C);

    int nG = BB * 9 * HWc;
    gather_kernel<<<(nG + 255) / 256, 256>>>(in, C);

    int K = 9 * C;
    int nW = Opad * K;
    repack_kernel<<<(nW + 255) / 256, 256>>>(w, O, Opad, C);

    dim3 grid(NN / 128, Opad / 128);
    dcn_gemm_kernel<<<grid, 256, GSMEM_TOTAL>>>(bias, out, K, O);
}

extern "C" void kernel_launch(void* const* d_in, const int* in_sizes, int n_in,
                              void* d_out, int out_size)
{
    const float* x   = (const float*)d_in[0];
    const float* ow1 = (const float*)d_in[1];
    const float* ob1 = (const float*)d_in[2];
    const float* w1  = (const float*)d_in[3];
    const float* b1  = (const float*)d_in[4];
    const float* ow2 = (const float*)d_in[5];
    const float* ob2 = (const float*)d_in[6];
    const float* w2  = (const float*)d_in[7];
    const float* b2  = (const float*)d_in[8];
    const float* ow3 = (const float*)d_in[9];
    const float* ob3 = (const float*)d_in[10];
    const float* w3  = (const float*)d_in[11];
    const float* b3  = (const float*)d_in[12];
    float* out = (float*)d_out;

    cudaFuncSetAttribute(dcn_gemm_kernel,
                         cudaFuncAttributeMaxDynamicSharedMemorySize, GSMEM_TOTAL);

    float *y1 = nullptr, *y2 = nullptr;
    cudaGetSymbolAddress((void**)&y1, g_y1);
    cudaGetSymbolAddress((void**)&y2, g_y2);

    run_layer(x,   64, ow1, ob1, w1, b1,  64, 128, y1);
    run_layer(y1,  64, ow2, ob2, w2, b2, 512, 512, y2);
    run_layer(y2, 512, ow3, ob3, w3, b3, 256, 256, out);
}

// round 13
// speedup vs baseline: 1.6430x; 1.3284x over previous
#include <cuda_runtime.h>
#include <cuda_fp16.h>
#include <math.h>
#include <stdint.h>

#define HH 96
#define WW 96
#define HWc 9216         // 96*96
#define BB 4
#define NN 36864         // BB*HWc

// ---------------- scratch (static device arrays; no cudaMalloc) --------------
__device__ uint16_t g_col[169869312];    // f16: [NN][K] K-major (K<=4608), 340MB
__device__ uint16_t g_wA[1179648];       // f16: [Opad][K] K-major
__device__ float    g_y1[2359296];       // 4*64*9216
__device__ float    g_y2[18874368];      // 4*512*9216
__device__ float    g_py[331776];        // 4*9*9216
__device__ float    g_px[331776];
__device__ float    g_mask[331776];

// ---------------- PTX helpers (generic compute_103-legal only) ---------------
__device__ __forceinline__ uint32_t smem_u32(const void* p) {
    uint32_t a;
    asm("{ .reg .u64 t; cvta.to.shared.u64 t, %1; cvt.u32.u64 %0, t; }"
        : "=r"(a) : "l"(p));
    return a;
}

__device__ __forceinline__ void cp16(uint32_t saddr, const void* g) {
    asm volatile("cp.async.cg.shared.global [%0], [%1], 16;"
                 :: "r"(saddr), "l"(g) : "memory");
}

__device__ __forceinline__ void cp_commit() {
    asm volatile("cp.async.commit_group;" ::: "memory");
}

template<int N>
__device__ __forceinline__ void cp_wait() {
    asm volatile("cp.async.wait_group %0;" :: "n"(N) : "memory");
}

__device__ __forceinline__ void ldsm4(uint32_t* r, uint32_t addr) {
    asm volatile("ldmatrix.sync.aligned.m8n8.x4.shared.b16 {%0,%1,%2,%3}, [%4];"
                 : "=r"(r[0]), "=r"(r[1]), "=r"(r[2]), "=r"(r[3]) : "r"(addr));
}

__device__ __forceinline__ void mma_f16(float* d, const uint32_t* a,
                                        const uint32_t* b) {
    asm volatile(
        "mma.sync.aligned.m16n8k16.row.col.f32.f16.f16.f32 "
        "{%0,%1,%2,%3}, {%4,%5,%6,%7}, {%8,%9}, {%0,%1,%2,%3};"
        : "+f"(d[0]), "+f"(d[1]), "+f"(d[2]), "+f"(d[3])
        : "r"(a[0]), "r"(a[1]), "r"(a[2]), "r"(a[3]), "r"(b[0]), "r"(b[1]));
}

// ---------------- 1) offset conv: om = conv3x3(x, ow) + ob -> py/px/mask -----
template<int CB>
__global__ void offset_conv_kernel(const float* __restrict__ x,
                                   const float* __restrict__ ow,
                                   const float* __restrict__ ob, int C)
{
    __shared__ float ws[CB * 9 * 28];
    const int tid = threadIdx.x;
    const int tx = tid & 31, ty = tid >> 5;
    const int w0 = blockIdx.x * 32 + tx;
    const int h0 = blockIdx.y * 8 + ty;
    const int b  = blockIdx.z;

    float acc[28];
#pragma unroll
    for (int i = 0; i < 28; i++) acc[i] = 0.f;

    for (int c0 = 0; c0 < C; c0 += CB) {
        __syncthreads();
        for (int i = tid; i < CB * 9 * 28; i += 256) {
            int oc  = i % 28;
            int r   = i / 28;
            int tap = r % 9;
            int cc  = r / 9;
            ws[i] = (oc < 27) ? ow[((size_t)oc * C + c0 + cc) * 9 + tap] : 0.f;
        }
        __syncthreads();

        for (int cc = 0; cc < CB; cc++) {
            const float* xp = x + ((size_t)b * C + c0 + cc) * HWc;
            float xv[9];
#pragma unroll
            for (int dy = 0; dy < 3; dy++)
#pragma unroll
                for (int dx = 0; dx < 3; dx++) {
                    int yy = h0 + dy - 1, xx = w0 + dx - 1;
                    bool v = (yy >= 0) & (yy < HH) & (xx >= 0) & (xx < WW);
                    xv[dy * 3 + dx] = v ? xp[yy * WW + xx] : 0.f;
                }
#pragma unroll
            for (int tap = 0; tap < 9; tap++) {
                const float* wr = &ws[(cc * 9 + tap) * 28];
                float xvv = xv[tap];
#pragma unroll
                for (int q = 0; q < 7; q++) {
                    float4 wv = *(const float4*)(wr + q * 4);
                    acc[q * 4 + 0] += xvv * wv.x;
                    acc[q * 4 + 1] += xvv * wv.y;
                    acc[q * 4 + 2] += xvv * wv.z;
                    acc[q * 4 + 3] += xvv * wv.w;
                }
            }
        }
    }

#pragma unroll
    for (int i = 0; i < 27; i++) acc[i] += ob[i];

    const int pix = h0 * WW + w0;
#pragma unroll
    for (int k = 0; k < 9; k++) {
        float oy = acc[2 * k];
        float ox = acc[2 * k + 1];
        float m  = 1.f / (1.f + __expf(-acc[18 + k]));
        int ky = k / 3, kx = k % 3;
        int idx = (b * 9 + k) * HWc + pix;
        g_py[idx]   = (float)(h0 + ky - 1) + oy;
        g_px[idx]   = (float)(w0 + kx - 1) + ox;
        g_mask[idx] = m;
    }
}

// ---------------- 2) deformable im2col gather -> g_col (f16, [N][K]) ---------
// Block = (32-pixel tile, k, b) x all C.  Phase A: hw-coalesced reads into a
// [64ch][32px] smem tile; Phase B: c-coalesced 128B stores (fixes the 4x DRAM
// write amplification of the K-strided per-thread layout).
__global__ void __launch_bounds__(256)
gather_kernel(const float* __restrict__ x, int C)
{
    __shared__ float    s_w[4][32];
    __shared__ int      s_o[4][32];
    __shared__ uint16_t s_t[64][33];

    const int tid = threadIdx.x;
    const int lane = tid & 31;
    const int ty   = tid >> 5;        // warp id, 0..7
    const int hw0 = blockIdx.x * 32;
    const int k   = blockIdx.y;
    const int b   = blockIdx.z;
    const int K   = 9 * C;

    if (tid < 32) {
        int idx = (b * 9 + k) * HWc + hw0 + tid;
        float pyv = g_py[idx], pxv = g_px[idx], m = g_mask[idx];
        float y0f = floorf(pyv), x0f = floorf(pxv);
        float wy = pyv - y0f, wx = pxv - x0f;
        int y0 = (int)y0f, x0 = (int)x0f;
        int y1 = y0 + 1, x1 = x0 + 1;
        float vy0 = (y0 >= 0 && y0 < HH) ? 1.f : 0.f;
        float vy1 = (y1 >= 0 && y1 < HH) ? 1.f : 0.f;
        float vx0 = (x0 >= 0 && x0 < WW) ? 1.f : 0.f;
        float vx1 = (x1 >= 0 && x1 < WW) ? 1.f : 0.f;
        s_w[0][tid] = (1.f - wy) * (1.f - wx) * m * vy0 * vx0;
        s_w[1][tid] = (1.f - wy) * wx         * m * vy0 * vx1;
        s_w[2][tid] = wy         * (1.f - wx) * m * vy1 * vx0;
        s_w[3][tid] = wy         * wx         * m * vy1 * vx1;
        int cy0 = min(max(y0, 0), HH - 1), cy1 = min(max(y1, 0), HH - 1);
        int cx0 = min(max(x0, 0), WW - 1), cx1 = min(max(x1, 0), WW - 1);
        s_o[0][tid] = cy0 * WW + cx0;
        s_o[1][tid] = cy0 * WW + cx1;
        s_o[2][tid] = cy1 * WW + cx0;
        s_o[3][tid] = cy1 * WW + cx1;
    }
    __syncthreads();

    const float w00 = s_w[0][lane], w01 = s_w[1][lane];
    const float w10 = s_w[2][lane], w11 = s_w[3][lane];
    const int   o00 = s_o[0][lane], o01 = s_o[1][lane];
    const int   o10 = s_o[2][lane], o11 = s_o[3][lane];
    const float* base = x + (size_t)b * C * HWc;

    for (int cblk = 0; cblk < C; cblk += 64) {
        // phase A: 8 channels per thread, lanes = 32 consecutive pixels
#pragma unroll
        for (int j = 0; j < 8; j++) {
            int cl = ty * 8 + j;
            const float* p = base + (size_t)(cblk + cl) * HWc;
            float v = w00 * p[o00] + w01 * p[o01] + w10 * p[o10] + w11 * p[o11];
            s_t[cl][lane] = __half_as_ushort(__float2half_rn(v));
        }
        __syncthreads();
        // phase B: warp ty writes pixels ty*4..ty*4+3, lanes over 32 c-pairs
#pragma unroll
        for (int h = 0; h < 4; h++) {
            int hwl = ty * 4 + h;
            uint32_t pk = (uint32_t)s_t[2 * lane][hwl] |
                          ((uint32_t)s_t[2 * lane + 1][hwl] << 16);
            size_t n = (size_t)b * HWc + hw0 + hwl;
            *reinterpret_cast<uint32_t*>(
                &g_col[n * (size_t)K + (size_t)k * C + cblk + 2 * lane]) = pk;
        }
        __syncthreads();
    }
}

// ---------------- 3a) weight repack: wA[o][tap*C+c] = f16(w[o][c][tap]) ------
__global__ void repack_kernel(const float* __restrict__ w,
                              int O, int Opad, int C)
{
    int K = 9 * C;
    int idx = blockIdx.x * blockDim.x + threadIdx.x;
    if (idx >= Opad * K) return;
    int kk = idx % K;
    int o  = idx / K;
    int tap = kk / C;
    int c   = kk % C;
    float v = (o < O) ? w[((size_t)o * C + c) * 9 + tap] : 0.f;
    g_wA[idx] = __half_as_ushort(__float2half_rn(v));
}

// ---------------- 3b) fp16 HMMA GEMM, 2-stage, 2 CTAs/SM ---------------------
// D[O,N] = wA · col^T.  CTA 128x128, 8 warps (4M x 2N), warp tile 32x64.
// KC=64 (128B rows), RS=144 padded stride (conflict-free ldmatrix).
// Grid: x = M-tile (fast) so co-resident CTAs of one N-tile share the B slice
// through L2 -> col read from DRAM once.
#define KC 64
#define RS 144
#define ASZ (128 * RS)           // one tile (A or B), 18432 B
#define STG (2 * ASZ)            // stage = 36864 B
#define GSMEM_TOTAL (2 * STG)    // 73728 B -> 2 CTAs/SM

__global__ void __launch_bounds__(256, 2)
dcn_gemm_kernel(const float* __restrict__ bias, float* __restrict__ out,
                int K, int O)
{
    extern __shared__ char smem[];
    const uint32_t sb = smem_u32(smem);
    const int tid = threadIdx.x, lid = tid & 31, wid = tid >> 5;
    const int warpM = wid & 3;        // 0..3 -> 32-row slices
    const int warpN = wid >> 2;       // 0..1 -> 64-col slices
    const int m0 = blockIdx.x * 128;  // M fast -> B-tile L2 reuse
    const int n0 = blockIdx.y * 128;

    float acc[2][8][4];
#pragma unroll
    for (int mt = 0; mt < 2; mt++)
#pragma unroll
        for (int nt = 0; nt < 8; nt++)
#pragma unroll
            for (int r = 0; r < 4; r++) acc[mt][nt][r] = 0.f;

    const char* pA = (const char*)g_wA  + (size_t)m0 * K * 2;
    const char* pB = (const char*)g_col + (size_t)n0 * K * 2;

    auto load_chunk = [&](int c, int buf) {
        size_t kb = (size_t)c * (KC * 2);
        uint32_t sbase = sb + (uint32_t)buf * STG;
#pragma unroll
        for (int i = 0; i < 8; i++) {
            int s   = tid + i * 256;
            int row = s >> 3;
            int seg = s & 7;
            const char* g;
            uint32_t so;
            if (row < 128) {
                g  = pA + (size_t)row * K * 2 + kb + (size_t)seg * 16;
                so = sbase + row * RS + seg * 16;
            } else {
                int r = row - 128;
                g  = pB + (size_t)r * K * 2 + kb + (size_t)seg * 16;
                so = sbase + ASZ + r * RS + seg * 16;
            }
            cp16(so, g);
        }
    };

    auto compute_chunk = [&](int buf) {
        uint32_t base = sb + (uint32_t)buf * STG;
        const uint32_t lrow = lid & 15;
        const uint32_t lcol = (lid >> 4) * 16;
#pragma unroll
        for (int ks = 0; ks < 4; ks++) {
            const uint32_t kb = ks * 32;
            uint32_t bb[8][2];
#pragma unroll
            for (int np = 0; np < 4; np++) {
                uint32_t t[4];
                uint32_t r = warpN * 64 + np * 16 + lrow;
                ldsm4(t, base + ASZ + r * RS + kb + lcol);
                bb[2 * np][0] = t[0]; bb[2 * np][1] = t[2];
                bb[2 * np + 1][0] = t[1]; bb[2 * np + 1][1] = t[3];
            }
            uint32_t af[2][4];
#pragma unroll
            for (int mt = 0; mt < 2; mt++) {
                uint32_t r = warpM * 32 + mt * 16 + lrow;
                ldsm4(af[mt], base + r * RS + kb + lcol);
            }
#pragma unroll
            for (int mt = 0; mt < 2; mt++)
#pragma unroll
                for (int nt = 0; nt < 8; nt++)
                    mma_f16(acc[mt][nt], af[mt], bb[nt]);
        }
    };

    const int nCh = K / KC;   // >= 9 always

    load_chunk(0, 0);
    cp_commit();

    for (int c = 0; c < nCh; c++) {
        int buf = c & 1;
        if (c + 1 < nCh) {
            load_chunk(c + 1, buf ^ 1);
            cp_commit();
            cp_wait<1>();
        } else {
            cp_wait<0>();
        }
        __syncthreads();
        compute_chunk(buf);
        __syncthreads();
    }

    // ---- epilogue: +bias, scatter into [B, O, H, W] -------------------------
    const int b   = n0 / HWc;
    const int hw0 = n0 % HWc;
    const int grp = lid >> 2;
    const int tig = lid & 3;
#pragma unroll
    for (int mt = 0; mt < 2; mt++) {
        int oA = m0 + warpM * 32 + mt * 16 + grp;
        int oB = oA + 8;
#pragma unroll
        for (int nt = 0; nt < 8; nt++) {
            int cn = warpN * 64 + nt * 8 + tig * 2;
            if (oA < O) {
                float bv = bias[oA];
                float2 v = make_float2(acc[mt][nt][0] + bv, acc[mt][nt][1] + bv);
                *(float2*)(out + ((size_t)b * O + oA) * HWc + hw0 + cn) = v;
            }
            if (oB < O) {
                float bv = bias[oB];
                float2 v = make_float2(acc[mt][nt][2] + bv, acc[mt][nt][3] + bv);
                *(float2*)(out + ((size_t)b * O + oB) * HWc + hw0 + cn) = v;
            }
        }
    }
}

// ---------------- host-side layer driver -------------------------------------
static void run_layer(const float* in, int C,
                      const float* ow, const float* obias,
                      const float* w, const float* bias,
                      int O, int Opad, float* out)
{
    dim3 gOff(WW / 32, HH / 8, BB);
    offset_conv_kernel<16><<<gOff, 256>>>(in, ow, obias, C);

    dim3 gG(HWc / 32, 9, BB);
    gather_kernel<<<gG, 256>>>(in, C);

    int K = 9 * C;
    int nW = Opad * K;
    repack_kernel<<<(nW + 255) / 256, 256>>>(w, O, Opad, C);

    dim3 grid(Opad / 128, NN / 128);
    dcn_gemm_kernel<<<grid, 256, GSMEM_TOTAL>>>(bias, out, K, O);
}

extern "C" void kernel_launch(void* const* d_in, const int* in_sizes, int n_in,
                              void* d_out, int out_size)
{
    const float* x   = (const float*)d_in[0];
    const float* ow1 = (const float*)d_in[1];
    const float* ob1 = (const float*)d_in[2];
    const float* w1  = (const float*)d_in[3];
    const float* b1  = (const float*)d_in[4];
    const float* ow2 = (const float*)d_in[5];
    const float* ob2 = (const float*)d_in[6];
    const float* w2  = (const float*)d_in[7];
    const float* b2  = (const float*)d_in[8];
    const float* ow3 = (const float*)d_in[9];
    const float* ob3 = (const float*)d_in[10];
    const float* w3  = (const float*)d_in[11];
    const float* b3  = (const float*)d_in[12];
    float* out = (float*)d_out;

    cudaFuncSetAttribute(dcn_gemm_kernel,
                         cudaFuncAttributeMaxDynamicSharedMemorySize, GSMEM_TOTAL);

    float *y1 = nullptr, *y2 = nullptr;
    cudaGetSymbolAddress((void**)&y1, g_y1);
    cudaGetSymbolAddress((void**)&y2, g_y2);

    run_layer(x,   64, ow1, ob1, w1, b1,  64, 128, y1);
    run_layer(y1,  64, ow2, ob2, w2, b2, 512, 512, y2);
    run_layer(y2, 512, ow3, ob3, w3, b3, 256, 256, out);
}

// round 14
// speedup vs baseline: 2.3439x; 1.4266x over previous
#include <cuda_runtime.h>
#include <cuda_fp16.h>
#include <math.h>
#include <stdint.h>

#define HH 96
#define WW 96
#define HWc 9216         // 96*96
#define BB 4
#define NN 36864         // BB*HWc

// ---------------- scratch (static device arrays; no cudaMalloc) --------------
__device__ uint16_t g_col[169869312];    // f16: deformable im2col [NN][K]
__device__ uint16_t g_colP[169869312];   // f16: plain im2col      [NN][K]
__device__ uint16_t g_wA[1179648];       // f16: [Opad][K] K-major (shared)
__device__ float    g_om[4718592];       // offset-conv out [BB][32][HWc]
__device__ float    g_y1[2359296];       // 4*64*9216
__device__ float    g_y2[18874368];      // 4*512*9216
__device__ float    g_py[331776];        // 4*9*9216
__device__ float    g_px[331776];
__device__ float    g_mask[331776];

// ---------------- PTX helpers (generic compute_103-legal only) ---------------
__device__ __forceinline__ uint32_t smem_u32(const void* p) {
    uint32_t a;
    asm("{ .reg .u64 t; cvta.to.shared.u64 t, %1; cvt.u32.u64 %0, t; }"
        : "=r"(a) : "l"(p));
    return a;
}

__device__ __forceinline__ void cp16(uint32_t saddr, const void* g) {
    asm volatile("cp.async.cg.shared.global [%0], [%1], 16;"
                 :: "r"(saddr), "l"(g) : "memory");
}

__device__ __forceinline__ void cp_commit() {
    asm volatile("cp.async.commit_group;" ::: "memory");
}

template<int N>
__device__ __forceinline__ void cp_wait() {
    asm volatile("cp.async.wait_group %0;" :: "n"(N) : "memory");
}

__device__ __forceinline__ void ldsm4(uint32_t* r, uint32_t addr) {
    asm volatile("ldmatrix.sync.aligned.m8n8.x4.shared.b16 {%0,%1,%2,%3}, [%4];"
                 : "=r"(r[0]), "=r"(r[1]), "=r"(r[2]), "=r"(r[3]) : "r"(addr));
}

__device__ __forceinline__ void mma_f16(float* d, const uint32_t* a,
                                        const uint32_t* b) {
    asm volatile(
        "mma.sync.aligned.m16n8k16.row.col.f32.f16.f16.f32 "
        "{%0,%1,%2,%3}, {%4,%5,%6,%7}, {%8,%9}, {%0,%1,%2,%3};"
        : "+f"(d[0]), "+f"(d[1]), "+f"(d[2]), "+f"(d[3])
        : "r"(a[0]), "r"(a[1]), "r"(a[2]), "r"(a[3]), "r"(b[0]), "r"(b[1]));
}

// ---------------- 1) plain im2col -> g_colP (f16, [N][K], zero-padded) -------
// Block = (32-pixel tile, tap k, b). Exact zero padding at image borders, so
// the downstream offset-conv GEMM is exact (no border fixup needed).
__global__ void __launch_bounds__(256)
plain_gather_kernel(const float* __restrict__ x, int C)
{
    __shared__ uint16_t s_t[64][33];

    const int tid  = threadIdx.x;
    const int lane = tid & 31;
    const int ty   = tid >> 5;        // warp id, 0..7
    const int hw0  = blockIdx.x * 32;
    const int k    = blockIdx.y;
    const int b    = blockIdx.z;
    const int K    = 9 * C;

    const int hw = hw0 + lane;
    const int r  = hw / WW, w = hw % WW;
    const int dr = k / 3 - 1, dc = k % 3 - 1;
    const int rr = r + dr, cc2 = w + dc;
    const bool valid = (rr >= 0) & (rr < HH) & (cc2 >= 0) & (cc2 < WW);
    const int src = valid ? (rr * WW + cc2) : 0;

    const float* base = x + (size_t)b * C * HWc;

    for (int cblk = 0; cblk < C; cblk += 64) {
#pragma unroll
        for (int j = 0; j < 8; j++) {
            int cl = ty * 8 + j;
            float v = valid ? base[(size_t)(cblk + cl) * HWc + src] : 0.f;
            s_t[cl][lane] = __half_as_ushort(__float2half_rn(v));
        }
        __syncthreads();
#pragma unroll
        for (int h = 0; h < 4; h++) {
            int hwl = ty * 4 + h;
            uint32_t pk = (uint32_t)s_t[2 * lane][hwl] |
                          ((uint32_t)s_t[2 * lane + 1][hwl] << 16);
            size_t n = (size_t)b * HWc + hw0 + hwl;
            *reinterpret_cast<uint32_t*>(
                &g_colP[n * (size_t)K + (size_t)k * C + cblk + 2 * lane]) = pk;
        }
        __syncthreads();
    }
}

// ---------------- 2) offset GEMM: om[27][N] = owA · colP^T  (BM=32) ----------
// CTA tile 32(M) x 256(N), 8 warps (1M x 8N), warp tile 32x32.
#define KC 64
#define RS 144
#define OASZ (32 * RS)
#define OSTG ((32 + 256) * RS)        // 41472 B
#define OSMEM_TOTAL (2 * OSTG)        // 82944 B

__global__ void __launch_bounds__(256, 2)
off_gemm_kernel(const float* __restrict__ bias, int K)
{
    extern __shared__ char smem[];
    const uint32_t sb = smem_u32(smem);
    const int tid = threadIdx.x, lid = tid & 31, wid = tid >> 5;
    const int warpN = wid;            // 0..7 -> 32-col slices
    const int n0 = blockIdx.y * 256;

    float acc[2][4][4];
#pragma unroll
    for (int mt = 0; mt < 2; mt++)
#pragma unroll
        for (int nt = 0; nt < 4; nt++)
#pragma unroll
            for (int rg = 0; rg < 4; rg++) acc[mt][nt][rg] = 0.f;

    const char* pA = (const char*)g_wA;
    const char* pB = (const char*)g_colP + (size_t)n0 * K * 2;

    auto load_chunk = [&](int c, int buf) {
        size_t kb = (size_t)c * (KC * 2);
        uint32_t sbase = sb + (uint32_t)buf * OSTG;
        // (32 + 256) rows x 8 segs = 2304 -> 9 per thread
#pragma unroll
        for (int i = 0; i < 9; i++) {
            int s   = tid + i * 256;
            int row = s >> 3;
            int seg = s & 7;
            const char* g;
            uint32_t so;
            if (row < 32) {
                g  = pA + (size_t)row * K * 2 + kb + (size_t)seg * 16;
                so = sbase + row * RS + seg * 16;
            } else {
                int rr = row - 32;
                g  = pB + (size_t)rr * K * 2 + kb + (size_t)seg * 16;
                so = sbase + OASZ + rr * RS + seg * 16;
            }
            cp16(so, g);
        }
    };

    auto compute_chunk = [&](int buf) {
        uint32_t base = sb + (uint32_t)buf * OSTG;
        const uint32_t lrow = lid & 15;
        const uint32_t lcol = (lid >> 4) * 16;
#pragma unroll
        for (int ks = 0; ks < 4; ks++) {
            const uint32_t kb = ks * 32;
            uint32_t bb[4][2];
#pragma unroll
            for (int np = 0; np < 2; np++) {
                uint32_t t[4];
                uint32_t rr = warpN * 32 + np * 16 + lrow;
                ldsm4(t, base + OASZ + rr * RS + kb + lcol);
                bb[2 * np][0] = t[0]; bb[2 * np][1] = t[2];
                bb[2 * np + 1][0] = t[1]; bb[2 * np + 1][1] = t[3];
            }
            uint32_t af[2][4];
#pragma unroll
            for (int mt = 0; mt < 2; mt++) {
                uint32_t rr = mt * 16 + lrow;
                ldsm4(af[mt], base + rr * RS + kb + lcol);
            }
#pragma unroll
            for (int mt = 0; mt < 2; mt++)
#pragma unroll
                for (int nt = 0; nt < 4; nt++)
                    mma_f16(acc[mt][nt], af[mt], bb[nt]);
        }
    };

    const int nCh = K / KC;

    load_chunk(0, 0);
    cp_commit();

    for (int c = 0; c < nCh; c++) {
        int buf = c & 1;
        if (c + 1 < nCh) {
            load_chunk(c + 1, buf ^ 1);
            cp_commit();
            cp_wait<1>();
        } else {
            cp_wait<0>();
        }
        __syncthreads();
        compute_chunk(buf);
        __syncthreads();
    }

    // epilogue: om[(b*32+o)*HWc + hw], only o<27
    const int b   = n0 / HWc;
    const int hw0 = n0 % HWc;
    const int grp = lid >> 2;
    const int tig = lid & 3;
#pragma unroll
    for (int mt = 0; mt < 2; mt++) {
        int oA = mt * 16 + grp;
        int oB = oA + 8;
#pragma unroll
        for (int nt = 0; nt < 4; nt++) {
            int cn = warpN * 32 + nt * 8 + tig * 2;
            if (oA < 27) {
                float bv = bias[oA];
                float2 v = make_float2(acc[mt][nt][0] + bv, acc[mt][nt][1] + bv);
                *(float2*)(g_om + ((size_t)b * 32 + oA) * HWc + hw0 + cn) = v;
            }
            if (oB < 27) {
                float bv = bias[oB];
                float2 v = make_float2(acc[mt][nt][2] + bv, acc[mt][nt][3] + bv);
                *(float2*)(g_om + ((size_t)b * 32 + oB) * HWc + hw0 + cn) = v;
            }
        }
    }
}

// ---------------- 3) py/px/mask from om --------------------------------------
__global__ void pypx_kernel()
{
    int n = blockIdx.x * blockDim.x + threadIdx.x;
    if (n >= NN) return;
    int b   = n / HWc;
    int pix = n % HWc;
    int r = pix / WW, w = pix % WW;
    const float* om = g_om + (size_t)b * 32 * HWc + pix;
#pragma unroll
    for (int k = 0; k < 9; k++) {
        float oy = om[(size_t)(2 * k) * HWc];
        float ox = om[(size_t)(2 * k + 1) * HWc];
        float mm = 1.f / (1.f + __expf(-om[(size_t)(18 + k) * HWc]));
        int idx = (b * 9 + k) * HWc + pix;
        g_py[idx]   = (float)(r + k / 3 - 1) + oy;
        g_px[idx]   = (float)(w + k % 3 - 1) + ox;
        g_mask[idx] = mm;
    }
}

// ---------------- 4) deformable im2col gather -> g_col (f16, [N][K]) ---------
__global__ void __launch_bounds__(256)
gather_kernel(const float* __restrict__ x, int C)
{
    __shared__ float    s_w[4][32];
    __shared__ int      s_o[4][32];
    __shared__ uint16_t s_t[64][33];

    const int tid = threadIdx.x;
    const int lane = tid & 31;
    const int ty   = tid >> 5;
    const int hw0 = blockIdx.x * 32;
    const int k   = blockIdx.y;
    const int b   = blockIdx.z;
    const int K   = 9 * C;

    if (tid < 32) {
        int idx = (b * 9 + k) * HWc + hw0 + tid;
        float pyv = g_py[idx], pxv = g_px[idx], m = g_mask[idx];
        float y0f = floorf(pyv), x0f = floorf(pxv);
        float wy = pyv - y0f, wx = pxv - x0f;
        int y0 = (int)y0f, x0 = (int)x0f;
        int y1 = y0 + 1, x1 = x0 + 1;
        float vy0 = (y0 >= 0 && y0 < HH) ? 1.f : 0.f;
        float vy1 = (y1 >= 0 && y1 < HH) ? 1.f : 0.f;
        float vx0 = (x0 >= 0 && x0 < WW) ? 1.f : 0.f;
        float vx1 = (x1 >= 0 && x1 < WW) ? 1.f : 0.f;
        s_w[0][tid] = (1.f - wy) * (1.f - wx) * m * vy0 * vx0;
        s_w[1][tid] = (1.f - wy) * wx         * m * vy0 * vx1;
        s_w[2][tid] = wy         * (1.f - wx) * m * vy1 * vx0;
        s_w[3][tid] = wy         * wx         * m * vy1 * vx1;
        int cy0 = min(max(y0, 0), HH - 1), cy1 = min(max(y1, 0), HH - 1);
        int cx0 = min(max(x0, 0), WW - 1), cx1 = min(max(x1, 0), WW - 1);
        s_o[0][tid] = cy0 * WW + cx0;
        s_o[1][tid] = cy0 * WW + cx1;
        s_o[2][tid] = cy1 * WW + cx0;
        s_o[3][tid] = cy1 * WW + cx1;
    }
    __syncthreads();

    const float w00 = s_w[0][lane], w01 = s_w[1][lane];
    const float w10 = s_w[2][lane], w11 = s_w[3][lane];
    const int   o00 = s_o[0][lane], o01 = s_o[1][lane];
    const int   o10 = s_o[2][lane], o11 = s_o[3][lane];
    const float* base = x + (size_t)b * C * HWc;

    for (int cblk = 0; cblk < C; cblk += 64) {
#pragma unroll
        for (int j = 0; j < 8; j++) {
            int cl = ty * 8 + j;
            const float* p = base + (size_t)(cblk + cl) * HWc;
            float v = w00 * p[o00] + w01 * p[o01] + w10 * p[o10] + w11 * p[o11];
            s_t[cl][lane] = __half_as_ushort(__float2half_rn(v));
        }
        __syncthreads();
#pragma unroll
        for (int h = 0; h < 4; h++) {
            int hwl = ty * 4 + h;
            uint32_t pk = (uint32_t)s_t[2 * lane][hwl] |
                          ((uint32_t)s_t[2 * lane + 1][hwl] << 16);
            size_t n = (size_t)b * HWc + hw0 + hwl;
            *reinterpret_cast<uint32_t*>(
                &g_col[n * (size_t)K + (size_t)k * C + cblk + 2 * lane]) = pk;
        }
        __syncthreads();
    }
}

// ---------------- 5a) weight repack: wA[o][tap*C+c] = f16(w[o][c][tap]) ------
__global__ void repack_kernel(const float* __restrict__ w,
                              int O, int Opad, int C)
{
    int K = 9 * C;
    int idx = blockIdx.x * blockDim.x + threadIdx.x;
    if (idx >= Opad * K) return;
    int kk = idx % K;
    int o  = idx / K;
    int tap = kk / C;
    int c   = kk % C;
    float v = (o < O) ? w[((size_t)o * C + c) * 9 + tap] : 0.f;
    g_wA[idx] = __half_as_ushort(__float2half_rn(v));
}

// ---------------- 5b) main fp16 HMMA GEMM, 2-stage, 2 CTAs/SM ----------------
#define ASZ (128 * RS)           // 18432 B
#define STG (2 * ASZ)            // 36864 B
#define GSMEM_TOTAL (2 * STG)    // 73728 B

__global__ void __launch_bounds__(256, 2)
dcn_gemm_kernel(const float* __restrict__ bias, float* __restrict__ out,
                int K, int O)
{
    extern __shared__ char smem[];
    const uint32_t sb = smem_u32(smem);
    const int tid = threadIdx.x, lid = tid & 31, wid = tid >> 5;
    const int warpM = wid & 3;
    const int warpN = wid >> 2;
    const int m0 = blockIdx.x * 128;  // M fast -> B-tile L2 reuse
    const int n0 = blockIdx.y * 128;

    float acc[2][8][4];
#pragma unroll
    for (int mt = 0; mt < 2; mt++)
#pragma unroll
        for (int nt = 0; nt < 8; nt++)
#pragma unroll
            for (int rg = 0; rg < 4; rg++) acc[mt][nt][rg] = 0.f;

    const char* pA = (const char*)g_wA  + (size_t)m0 * K * 2;
    const char* pB = (const char*)g_col + (size_t)n0 * K * 2;

    auto load_chunk = [&](int c, int buf) {
        size_t kb = (size_t)c * (KC * 2);
        uint32_t sbase = sb + (uint32_t)buf * STG;
#pragma unroll
        for (int i = 0; i < 8; i++) {
            int s   = tid + i * 256;
            int row = s >> 3;
            int seg = s & 7;
            const char* g;
            uint32_t so;
            if (row < 128) {
                g  = pA + (size_t)row * K * 2 + kb + (size_t)seg * 16;
                so = sbase + row * RS + seg * 16;
            } else {
                int rr = row - 128;
                g  = pB + (size_t)rr * K * 2 + kb + (size_t)seg * 16;
                so = sbase + ASZ + rr * RS + seg * 16;
            }
            cp16(so, g);
        }
    };

    auto compute_chunk = [&](int buf) {
        uint32_t base = sb + (uint32_t)buf * STG;
        const uint32_t lrow = lid & 15;
        const uint32_t lcol = (lid >> 4) * 16;
#pragma unroll
        for (int ks = 0; ks < 4; ks++) {
            const uint32_t kb = ks * 32;
            uint32_t bb[8][2];
#pragma unroll
            for (int np = 0; np < 4; np++) {
                uint32_t t[4];
                uint32_t rr = warpN * 64 + np * 16 + lrow;
                ldsm4(t, base + ASZ + rr * RS + kb + lcol);
                bb[2 * np][0] = t[0]; bb[2 * np][1] = t[2];
                bb[2 * np + 1][0] = t[1]; bb[2 * np + 1][1] = t[3];
            }
            uint32_t af[2][4];
#pragma unroll
            for (int mt = 0; mt < 2; mt++) {
                uint32_t rr = warpM * 32 + mt * 16 + lrow;
                ldsm4(af[mt], base + rr * RS + kb + lcol);
            }
#pragma unroll
            for (int mt = 0; mt < 2; mt++)
#pragma unroll
                for (int nt = 0; nt < 8; nt++)
                    mma_f16(acc[mt][nt], af[mt], bb[nt]);
        }
    };

    const int nCh = K / KC;

    load_chunk(0, 0);
    cp_commit();

    for (int c = 0; c < nCh; c++) {
        int buf = c & 1;
        if (c + 1 < nCh) {
            load_chunk(c + 1, buf ^ 1);
            cp_commit();
            cp_wait<1>();
        } else {
            cp_wait<0>();
        }
        __syncthreads();
        compute_chunk(buf);
        __syncthreads();
    }

    const int b   = n0 / HWc;
    const int hw0 = n0 % HWc;
    const int grp = lid >> 2;
    const int tig = lid & 3;
#pragma unroll
    for (int mt = 0; mt < 2; mt++) {
        int oA = m0 + warpM * 32 + mt * 16 + grp;
        int oB = oA + 8;
#pragma unroll
        for (int nt = 0; nt < 8; nt++) {
            int cn = warpN * 64 + nt * 8 + tig * 2;
            if (oA < O) {
                float bv = bias[oA];
                float2 v = make_float2(acc[mt][nt][0] + bv, acc[mt][nt][1] + bv);
                *(float2*)(out + ((size_t)b * O + oA) * HWc + hw0 + cn) = v;
            }
            if (oB < O) {
                float bv = bias[oB];
                float2 v = make_float2(acc[mt][nt][2] + bv, acc[mt][nt][3] + bv);
                *(float2*)(out + ((size_t)b * O + oB) * HWc + hw0 + cn) = v;
            }
        }
    }
}

// ---------------- host-side layer driver -------------------------------------
static void run_layer(const float* in, int C,
                      const float* ow, const float* obias,
                      const float* w, const float* bias,
                      int O, int Opad, float* out)
{
    int K = 9 * C;

    // offset path: plain im2col -> offset GEMM -> py/px/mask
    dim3 gG(HWc / 32, 9, BB);
    plain_gather_kernel<<<gG, 256>>>(in, C);

    repack_kernel<<<(32 * K + 255) / 256, 256>>>(ow, 27, 32, C);

    dim3 gOff(1, NN / 256);
    off_gemm_kernel<<<gOff, 256, OSMEM_TOTAL>>>(obias, K);

    pypx_kernel<<<(NN + 255) / 256, 256>>>();

    // main path: deformable im2col -> main GEMM
    gather_kernel<<<gG, 256>>>(in, C);

    repack_kernel<<<(Opad * K + 255) / 256, 256>>>(w, O, Opad, C);

    dim3 grid(Opad / 128, NN / 128);
    dcn_gemm_kernel<<<grid, 256, GSMEM_TOTAL>>>(bias, out, K, O);
}

extern "C" void kernel_launch(void* const* d_in, const int* in_sizes, int n_in,
                              void* d_out, int out_size)
{
    const float* x   = (const float*)d_in[0];
    const float* ow1 = (const float*)d_in[1];
    const float* ob1 = (const float*)d_in[2];
    const float* w1  = (const float*)d_in[3];
    const float* b1  = (const float*)d_in[4];
    const float* ow2 = (const float*)d_in[5];
    const float* ob2 = (const float*)d_in[6];
    const float* w2  = (const float*)d_in[7];
    const float* b2  = (const float*)d_in[8];
    const float* ow3 = (const float*)d_in[9];
    const float* ob3 = (const float*)d_in[10];
    const float* w3  = (const float*)d_in[11];
    const float* b3  = (const float*)d_in[12];
    float* out = (float*)d_out;

    cudaFuncSetAttribute(dcn_gemm_kernel,
                         cudaFuncAttributeMaxDynamicSharedMemorySize, GSMEM_TOTAL);
    cudaFuncSetAttribute(off_gemm_kernel,
                         cudaFuncAttributeMaxDynamicSharedMemorySize, OSMEM_TOTAL);

    float *y1 = nullptr, *y2 = nullptr;
    cudaGetSymbolAddress((void**)&y1, g_y1);
    cudaGetSymbolAddress((void**)&y2, g_y2);

    run_layer(x,   64, ow1, ob1, w1, b1,  64, 128, y1);
    run_layer(y1,  64, ow2, ob2, w2, b2, 512, 512, y2);
    run_layer(y2, 512, ow3, ob3, w3, b3, 256, 256, out);
}

// round 15
// speedup vs baseline: 2.8348x; 1.2095x over previous
#include <cuda_runtime.h>
#include <cuda_fp16.h>
#include <math.h>
#include <stdint.h>

#define HH 96
#define WW 96
#define HWc 9216         // 96*96
#define BB 4
#define NN 36864         // BB*HWc

// ---------------- scratch (static device arrays; no cudaMalloc) --------------
__device__ uint16_t g_col[169869312];    // f16: deformable im2col [NN][K]
__device__ uint16_t g_wA[1179648];       // f16: [Opad][K] K-major (shared)
__device__ float    g_xt32[2359296];     // x  transposed [n][64] fp32
__device__ uint16_t g_xt16[2359296];     // x  transposed [n][64] f16
__device__ float    g_y1t32[2359296];    // y1 [n][64] fp32
__device__ uint16_t g_y1t16[2359296];    // y1 [n][64] f16
__device__ float    g_y2t32[18874368];   // y2 [n][512] fp32
__device__ uint16_t g_y2t16[18874368];   // y2 [n][512] f16
__device__ float    g_py[331776];        // 4*9*9216
__device__ float    g_px[331776];
__device__ float    g_mask[331776];

// ---------------- PTX helpers (generic compute_103-legal only) ---------------
__device__ __forceinline__ uint32_t smem_u32(const void* p) {
    uint32_t a;
    asm("{ .reg .u64 t; cvta.to.shared.u64 t, %1; cvt.u32.u64 %0, t; }"
        : "=r"(a) : "l"(p));
    return a;
}

__device__ __forceinline__ void cp16(uint32_t saddr, const void* g) {
    asm volatile("cp.async.cg.shared.global [%0], [%1], 16;"
                 :: "r"(saddr), "l"(g) : "memory");
}

// cp.async with runtime src-size: bytes beyond src_sz are zero-filled.
__device__ __forceinline__ void cp16z(uint32_t saddr, const void* g, uint32_t src_sz) {
    asm volatile("cp.async.cg.shared.global [%0], [%1], 16, %2;"
                 :: "r"(saddr), "l"(g), "r"(src_sz) : "memory");
}

__device__ __forceinline__ void cp_commit() {
    asm volatile("cp.async.commit_group;" ::: "memory");
}

template<int N>
__device__ __forceinline__ void cp_wait() {
    asm volatile("cp.async.wait_group %0;" :: "n"(N) : "memory");
}

__device__ __forceinline__ void ldsm4(uint32_t* r, uint32_t addr) {
    asm volatile("ldmatrix.sync.aligned.m8n8.x4.shared.b16 {%0,%1,%2,%3}, [%4];"
                 : "=r"(r[0]), "=r"(r[1]), "=r"(r[2]), "=r"(r[3]) : "r"(addr));
}

__device__ __forceinline__ void mma_f16(float* d, const uint32_t* a,
                                        const uint32_t* b) {
    asm volatile(
        "mma.sync.aligned.m16n8k16.row.col.f32.f16.f16.f32 "
        "{%0,%1,%2,%3}, {%4,%5,%6,%7}, {%8,%9}, {%0,%1,%2,%3};"
        : "+f"(d[0]), "+f"(d[1]), "+f"(d[2]), "+f"(d[3])
        : "r"(a[0]), "r"(a[1]), "r"(a[2]), "r"(a[3]), "r"(b[0]), "r"(b[1]));
}

// ---------------- 0) transpose x: [b][c][hw] fp32 -> [n][c] fp32+f16 ---------
__global__ void __launch_bounds__(256)
transpose_x_kernel(const float* __restrict__ x)
{
    __shared__ float s[32][33];
    const int tid = threadIdx.x;
    const int tx = tid & 31, ty = tid >> 5;
    const int hw0 = blockIdx.x * 32;
    const int c0  = blockIdx.y * 32;
    const int b   = blockIdx.z;
#pragma unroll
    for (int j = 0; j < 4; j++)
        s[ty + 8 * j][tx] = x[((size_t)b * 64 + c0 + ty + 8 * j) * HWc + hw0 + tx];
    __syncthreads();
#pragma unroll
    for (int j = 0; j < 4; j++) {
        float v = s[tx][ty + 8 * j];
        size_t n = (size_t)b * HWc + hw0 + ty + 8 * j;
        g_xt32[n * 64 + c0 + tx] = v;
        g_xt16[n * 64 + c0 + tx] = __half_as_ushort(__float2half_rn(v));
    }
}

// ---------------- 1) offset GEMM with implicit plain-im2col B ----------------
// om[27][N] = owA · B^T where B[n][tap*C+c] = y16[shift(n,tap)][c] (zero-pad).
// CTA tile 32(M) x 256(N), 8 warps (1M x 8N). Epilogue computes py/px/mask.
#define KC 64
#define RS 144
#define OASZ (32 * RS)
#define OSTG ((32 + 256) * RS)        // 41472 B
#define OSMEM_TOTAL (2 * OSTG)        // 82944 B

__global__ void __launch_bounds__(256, 2)
off_gemm_kernel(const float* __restrict__ bias,
                const uint16_t* __restrict__ y16, int C)
{
    extern __shared__ char smem[];
    const uint32_t sb = smem_u32(smem);
    const int tid = threadIdx.x, lid = tid & 31, wid = tid >> 5;
    const int warpN = wid;
    const int n0 = blockIdx.x * 256;
    const int K = 9 * C;
    const int cpt = C >> 6;           // chunks per tap

    float acc[2][4][4];
#pragma unroll
    for (int mt = 0; mt < 2; mt++)
#pragma unroll
        for (int nt = 0; nt < 4; nt++)
#pragma unroll
            for (int rg = 0; rg < 4; rg++) acc[mt][nt][rg] = 0.f;

    const char* pA = (const char*)g_wA;

    auto load_chunk = [&](int ch, int buf) {
        uint32_t sbase = sb + (uint32_t)buf * OSTG;
        int tap = ch / cpt;
        int coff = (ch - tap * cpt) * 64;
        int dr = tap / 3 - 1, dc = tap % 3 - 1;
#pragma unroll
        for (int i = 0; i < 9; i++) {
            int s   = tid + i * 256;
            int row = s >> 3;
            int seg = s & 7;
            if (row < 32) {
                const char* g = pA + (size_t)row * K * 2 + (size_t)ch * 128
                                + (size_t)seg * 16;
                cp16(sbase + row * RS + seg * 16, g);
            } else {
                int rt = row - 32;
                int n = n0 + rt;
                int b = n / HWc;
                int pix = n - b * HWc;
                int r = pix / WW, w = pix - r * WW;
                int rr = r + dr, cc = w + dc;
                bool v = (rr >= 0) & (rr < HH) & (cc >= 0) & (cc < WW);
                size_t src_n = (size_t)b * HWc + (v ? (rr * WW + cc) : 0);
                const char* g = (const char*)y16 + (src_n * C + coff) * 2
                                + (size_t)seg * 16;
                cp16z(sbase + OASZ + rt * RS + seg * 16, g, v ? 16u : 0u);
            }
        }
    };

    auto compute_chunk = [&](int buf) {
        uint32_t base = sb + (uint32_t)buf * OSTG;
        const uint32_t lrow = lid & 15;
        const uint32_t lcol = (lid >> 4) * 16;
#pragma unroll
        for (int ks = 0; ks < 4; ks++) {
            const uint32_t kb = ks * 32;
            uint32_t bb[4][2];
#pragma unroll
            for (int np = 0; np < 2; np++) {
                uint32_t t[4];
                uint32_t rr = warpN * 32 + np * 16 + lrow;
                ldsm4(t, base + OASZ + rr * RS + kb + lcol);
                bb[2 * np][0] = t[0]; bb[2 * np][1] = t[2];
                bb[2 * np + 1][0] = t[1]; bb[2 * np + 1][1] = t[3];
            }
            uint32_t af[2][4];
#pragma unroll
            for (int mt = 0; mt < 2; mt++) {
                uint32_t rr = mt * 16 + lrow;
                ldsm4(af[mt], base + rr * RS + kb + lcol);
            }
#pragma unroll
            for (int mt = 0; mt < 2; mt++)
#pragma unroll
                for (int nt = 0; nt < 4; nt++)
                    mma_f16(acc[mt][nt], af[mt], bb[nt]);
        }
    };

    const int nCh = K / KC;

    load_chunk(0, 0);
    cp_commit();

    for (int c = 0; c < nCh; c++) {
        int buf = c & 1;
        if (c + 1 < nCh) {
            load_chunk(c + 1, buf ^ 1);
            cp_commit();
            cp_wait<1>();
        } else {
            cp_wait<0>();
        }
        __syncthreads();
        compute_chunk(buf);
        __syncthreads();
    }

    // ---- fused epilogue: stage om tile, compute py/px/mask ------------------
    float* s_om = (float*)smem;          // [27][264]
    const int grp = lid >> 2;
    const int tig = lid & 3;
#pragma unroll
    for (int mt = 0; mt < 2; mt++) {
        int oA = mt * 16 + grp;
        int oB = oA + 8;
#pragma unroll
        for (int nt = 0; nt < 4; nt++) {
            int cn = warpN * 32 + nt * 8 + tig * 2;
            if (oA < 27) {
                float bv = bias[oA];
                s_om[oA * 264 + cn]     = acc[mt][nt][0] + bv;
                s_om[oA * 264 + cn + 1] = acc[mt][nt][1] + bv;
            }
            if (oB < 27) {
                float bv = bias[oB];
                s_om[oB * 264 + cn]     = acc[mt][nt][2] + bv;
                s_om[oB * 264 + cn + 1] = acc[mt][nt][3] + bv;
            }
        }
    }
    __syncthreads();

    {
        int n = n0 + tid;
        int b = n / HWc;
        int pix = n - b * HWc;
        int r = pix / WW, w = pix - r * WW;
#pragma unroll
        for (int k = 0; k < 9; k++) {
            float oy = s_om[(2 * k) * 264 + tid];
            float ox = s_om[(2 * k + 1) * 264 + tid];
            float mm = 1.f / (1.f + __expf(-s_om[(18 + k) * 264 + tid]));
            int idx = (b * 9 + k) * HWc + pix;
            g_py[idx]   = (float)(r + k / 3 - 1) + oy;
            g_px[idx]   = (float)(w + k % 3 - 1) + ox;
            g_mask[idx] = mm;
        }
    }
}

// ---------------- 2) deformable gather (streaming) -> g_col [n][K] f16 -------
// Warp owns one n; loops taps k; lanes stream contiguous c from y32 [n][c].
__global__ void __launch_bounds__(256)
gather_kernel(const float* __restrict__ y32, int C)
{
    const int lane = threadIdx.x & 31;
    const int wid  = threadIdx.x >> 5;
    const int n = blockIdx.x * 8 + wid;
    const int b = n / HWc;
    const int pix = n - b * HWc;
    const int K = 9 * C;

    const float* base = y32 + (size_t)b * HWc * C;
    const size_t outB = (size_t)n * K;

#pragma unroll
    for (int k = 0; k < 9; k++) {
        int idx = (b * 9 + k) * HWc + pix;
        float pyv = g_py[idx], pxv = g_px[idx], m = g_mask[idx];
        float y0f = floorf(pyv), x0f = floorf(pxv);
        float wy = pyv - y0f, wx = pxv - x0f;
        int y0 = (int)y0f, x0 = (int)x0f;
        int y1 = y0 + 1, x1 = x0 + 1;
        float vy0 = (y0 >= 0 && y0 < HH) ? 1.f : 0.f;
        float vy1 = (y1 >= 0 && y1 < HH) ? 1.f : 0.f;
        float vx0 = (x0 >= 0 && x0 < WW) ? 1.f : 0.f;
        float vx1 = (x1 >= 0 && x1 < WW) ? 1.f : 0.f;
        float w00 = (1.f - wy) * (1.f - wx) * m * vy0 * vx0;
        float w01 = (1.f - wy) * wx         * m * vy0 * vx1;
        float w10 = wy         * (1.f - wx) * m * vy1 * vx0;
        float w11 = wy         * wx         * m * vy1 * vx1;
        int cy0 = min(max(y0, 0), HH - 1), cy1 = min(max(y1, 0), HH - 1);
        int cx0 = min(max(x0, 0), WW - 1), cx1 = min(max(x1, 0), WW - 1);
        const float* p00 = base + (size_t)(cy0 * WW + cx0) * C;
        const float* p01 = base + (size_t)(cy0 * WW + cx1) * C;
        const float* p10 = base + (size_t)(cy1 * WW + cx0) * C;
        const float* p11 = base + (size_t)(cy1 * WW + cx1) * C;

        for (int cb = 0; cb < C; cb += 64) {
            int c = cb + 2 * lane;
            float2 v00 = *(const float2*)(p00 + c);
            float2 v01 = *(const float2*)(p01 + c);
            float2 v10 = *(const float2*)(p10 + c);
            float2 v11 = *(const float2*)(p11 + c);
            float a = w00 * v00.x + w01 * v01.x + w10 * v10.x + w11 * v11.x;
            float d = w00 * v00.y + w01 * v01.y + w10 * v10.y + w11 * v11.y;
            uint32_t pk = (uint32_t)__half_as_ushort(__float2half_rn(a)) |
                          ((uint32_t)__half_as_ushort(__float2half_rn(d)) << 16);
            *reinterpret_cast<uint32_t*>(&g_col[outB + (size_t)k * C + c]) = pk;
        }
    }
}

// ---------------- 3a) weight repack: wA[o][tap*C+c] = f16(w[o][c][tap]) ------
__global__ void repack_kernel(const float* __restrict__ w,
                              int O, int Opad, int C)
{
    int K = 9 * C;
    int idx = blockIdx.x * blockDim.x + threadIdx.x;
    if (idx >= Opad * K) return;
    int kk = idx % K;
    int o  = idx / K;
    int tap = kk / C;
    int c   = kk % C;
    float v = (o < O) ? w[((size_t)o * C + c) * 9 + tap] : 0.f;
    g_wA[idx] = __half_as_ushort(__float2half_rn(v));
}

// ---------------- 3b) main fp16 HMMA GEMM, 2-stage, 2 CTAs/SM ----------------
// MODE 0: out = fp32 [b][O][hw] (harness).  MODE 1: y32 [n][O] + y16 [n][O].
#define ASZ (128 * RS)           // 18432 B
#define STG (2 * ASZ)            // 36864 B
#define GSMEM_TOTAL (2 * STG)    // 73728 B

template<int MODE>
__global__ void __launch_bounds__(256, 2)
dcn_gemm_kernel(const float* __restrict__ bias, float* __restrict__ out,
                uint16_t* __restrict__ out16, int K, int O)
{
    extern __shared__ char smem[];
    const uint32_t sb = smem_u32(smem);
    const int tid = threadIdx.x, lid = tid & 31, wid = tid >> 5;
    const int warpM = wid & 3;
    const int warpN = wid >> 2;
    const int m0 = blockIdx.x * 128;  // M fast -> B-tile L2 reuse
    const int n0 = blockIdx.y * 128;

    float acc[2][8][4];
#pragma unroll
    for (int mt = 0; mt < 2; mt++)
#pragma unroll
        for (int nt = 0; nt < 8; nt++)
#pragma unroll
            for (int rg = 0; rg < 4; rg++) acc[mt][nt][rg] = 0.f;

    const char* pA = (const char*)g_wA  + (size_t)m0 * K * 2;
    const char* pB = (const char*)g_col + (size_t)n0 * K * 2;

    auto load_chunk = [&](int c, int buf) {
        size_t kb = (size_t)c * (KC * 2);
        uint32_t sbase = sb + (uint32_t)buf * STG;
#pragma unroll
        for (int i = 0; i < 8; i++) {
            int s   = tid + i * 256;
            int row = s >> 3;
            int seg = s & 7;
            const char* g;
            uint32_t so;
            if (row < 128) {
                g  = pA + (size_t)row * K * 2 + kb + (size_t)seg * 16;
                so = sbase + row * RS + seg * 16;
            } else {
                int rr = row - 128;
                g  = pB + (size_t)rr * K * 2 + kb + (size_t)seg * 16;
                so = sbase + ASZ + rr * RS + seg * 16;
            }
            cp16(so, g);
        }
    };

    auto compute_chunk = [&](int buf) {
        uint32_t base = sb + (uint32_t)buf * STG;
        const uint32_t lrow = lid & 15;
        const uint32_t lcol = (lid >> 4) * 16;
#pragma unroll
        for (int ks = 0; ks < 4; ks++) {
            const uint32_t kb = ks * 32;
            uint32_t bb[8][2];
#pragma unroll
            for (int np = 0; np < 4; np++) {
                uint32_t t[4];
                uint32_t rr = warpN * 64 + np * 16 + lrow;
                ldsm4(t, base + ASZ + rr * RS + kb + lcol);
                bb[2 * np][0] = t[0]; bb[2 * np][1] = t[2];
                bb[2 * np + 1][0] = t[1]; bb[2 * np + 1][1] = t[3];
            }
            uint32_t af[2][4];
#pragma unroll
            for (int mt = 0; mt < 2; mt++) {
                uint32_t rr = warpM * 32 + mt * 16 + lrow;
                ldsm4(af[mt], base + rr * RS + kb + lcol);
            }
#pragma unroll
            for (int mt = 0; mt < 2; mt++)
#pragma unroll
                for (int nt = 0; nt < 8; nt++)
                    mma_f16(acc[mt][nt], af[mt], bb[nt]);
        }
    };

    const int nCh = K / KC;

    load_chunk(0, 0);
    cp_commit();

    for (int c = 0; c < nCh; c++) {
        int buf = c & 1;
        if (c + 1 < nCh) {
            load_chunk(c + 1, buf ^ 1);
            cp_commit();
            cp_wait<1>();
        } else {
            cp_wait<0>();
        }
        __syncthreads();
        compute_chunk(buf);
        __syncthreads();
    }

    const int grp = lid >> 2;
    const int tig = lid & 3;

    if (MODE == 0) {
        const int b   = n0 / HWc;
        const int hw0 = n0 % HWc;
#pragma unroll
        for (int mt = 0; mt < 2; mt++) {
            int oA = m0 + warpM * 32 + mt * 16 + grp;
            int oB = oA + 8;
#pragma unroll
            for (int nt = 0; nt < 8; nt++) {
                int cn = warpN * 64 + nt * 8 + tig * 2;
                if (oA < O) {
                    float bv = bias[oA];
                    float2 v = make_float2(acc[mt][nt][0] + bv, acc[mt][nt][1] + bv);
                    *(float2*)(out + ((size_t)b * O + oA) * HWc + hw0 + cn) = v;
                }
                if (oB < O) {
                    float bv = bias[oB];
                    float2 v = make_float2(acc[mt][nt][2] + bv, acc[mt][nt][3] + bv);
                    *(float2*)(out + ((size_t)b * O + oB) * HWc + hw0 + cn) = v;
                }
            }
        }
    } else {
        // stage [n_local][o_local] fp32 tile in smem, then coalesced [n][c] writes
        float* s32 = (float*)smem;       // pitch 132
        __syncthreads();                 // all ldsm on smem done
#pragma unroll
        for (int mt = 0; mt < 2; mt++) {
            int oAl = warpM * 32 + mt * 16 + grp;
            int oBl = oAl + 8;
            float bvA = (m0 + oAl < O) ? bias[m0 + oAl] : 0.f;
            float bvB = (m0 + oBl < O) ? bias[m0 + oBl] : 0.f;
#pragma unroll
            for (int nt = 0; nt < 8; nt++) {
                int cn = warpN * 64 + nt * 8 + tig * 2;
                s32[(size_t)cn * 132 + oAl]       = acc[mt][nt][0] + bvA;
                s32[(size_t)(cn + 1) * 132 + oAl] = acc[mt][nt][1] + bvA;
                s32[(size_t)cn * 132 + oBl]       = acc[mt][nt][2] + bvB;
                s32[(size_t)(cn + 1) * 132 + oBl] = acc[mt][nt][3] + bvB;
            }
        }
        __syncthreads();
        const int row  = tid >> 1;          // 0..127 (n local)
        const int half = tid & 1;           // 0..1 (64 cols each)
        const size_t n = (size_t)(n0 + row);
#pragma unroll
        for (int j = 0; j < 16; j++) {
            int col = half * 64 + j * 4;
            int o = m0 + col;
            if (o < O) {
                float4 v = *(float4*)(s32 + (size_t)row * 132 + col);
                *(float4*)(out + n * O + o) = v;
                __half2 h0 = __floats2half2_rn(v.x, v.y);
                __half2 h1 = __floats2half2_rn(v.z, v.w);
                uint2 pk;
                pk.x = *(uint32_t*)&h0;
                pk.y = *(uint32_t*)&h1;
                *(uint2*)(out16 + n * O + o) = pk;
            }
        }
    }
}

// ---------------- host-side layer driver -------------------------------------
static void run_layer(const float* in32, const uint16_t* in16, int C,
                      const float* ow, const float* obias,
                      const float* w, const float* bias,
                      int O, int Opad, int mode, float* out, uint16_t* out16)
{
    int K = 9 * C;

    // offset path: implicit-im2col GEMM -> py/px/mask (fused)
    repack_kernel<<<(32 * K + 255) / 256, 256>>>(ow, 27, 32, C);
    off_gemm_kernel<<<NN / 256, 256, OSMEM_TOTAL>>>(obias, in16, C);

    // main path: streaming deformable gather -> main GEMM
    gather_kernel<<<NN / 8, 256>>>(in32, C);
    repack_kernel<<<(Opad * K + 255) / 256, 256>>>(w, O, Opad, C);

    dim3 grid(Opad / 128, NN / 128);
    if (mode == 0)
        dcn_gemm_kernel<0><<<grid, 256, GSMEM_TOTAL>>>(bias, out, out16, K, O);
    else
        dcn_gemm_kernel<1><<<grid, 256, GSMEM_TOTAL>>>(bias, out, out16, K, O);
}

extern "C" void kernel_launch(void* const* d_in, const int* in_sizes, int n_in,
                              void* d_out, int out_size)
{
    const float* x   = (const float*)d_in[0];
    const float* ow1 = (const float*)d_in[1];
    const float* ob1 = (const float*)d_in[2];
    const float* w1  = (const float*)d_in[3];
    const float* b1  = (const float*)d_in[4];
    const float* ow2 = (const float*)d_in[5];
    const float* ob2 = (const float*)d_in[6];
    const float* w2  = (const float*)d_in[7];
    const float* b2  = (const float*)d_in[8];
    const float* ow3 = (const float*)d_in[9];
    const float* ob3 = (const float*)d_in[10];
    const float* w3  = (const float*)d_in[11];
    const float* b3  = (const float*)d_in[12];
    float* out = (float*)d_out;

    cudaFuncSetAttribute(dcn_gemm_kernel<0>,
                         cudaFuncAttributeMaxDynamicSharedMemorySize, GSMEM_TOTAL);
    cudaFuncSetAttribute(dcn_gemm_kernel<1>,
                         cudaFuncAttributeMaxDynamicSharedMemorySize, GSMEM_TOTAL);
    cudaFuncSetAttribute(off_gemm_kernel,
                         cudaFuncAttributeMaxDynamicSharedMemorySize, OSMEM_TOTAL);

    float *xt32, *y1t32, *y2t32;
    uint16_t *xt16, *y1t16, *y2t16;
    cudaGetSymbolAddress((void**)&xt32,  g_xt32);
    cudaGetSymbolAddress((void**)&xt16,  g_xt16);
    cudaGetSymbolAddress((void**)&y1t32, g_y1t32);
    cudaGetSymbolAddress((void**)&y1t16, g_y1t16);
    cudaGetSymbolAddress((void**)&y2t32, g_y2t32);
    cudaGetSymbolAddress((void**)&y2t16, g_y2t16);

    dim3 gT(HWc / 32, 2, BB);
    transpose_x_kernel<<<gT, 256>>>(x);

    run_layer(xt32,  xt16,  64,  ow1, ob1, w1, b1,  64, 128, 1, y1t32, y1t16);
    run_layer(y1t32, y1t16, 64,  ow2, ob2, w2, b2, 512, 512, 1, y2t32, y2t16);
    run_layer(y2t32, y2t16, 512, ow3, ob3, w3, b3, 256, 256, 0, out, nullptr);
}

// round 16
// speedup vs baseline: 2.9534x; 1.0418x over previous
#include <cuda_runtime.h>
#include <cuda_fp16.h>
#include <math.h>
#include <stdint.h>

#define HH 96
#define WW 96
#define HWc 9216         // 96*96
#define BB 4
#define NN 36864         // BB*HWc

// ---------------- scratch (static device arrays; no cudaMalloc) --------------
__device__ uint16_t g_col[169869312];    // f16: deformable im2col [NN][K]
__device__ uint16_t g_wA[1179648];       // f16: [Opad][K] K-major (shared)
__device__ float    g_xt32[2359296];     // x  transposed [n][64] fp32
__device__ uint16_t g_xt16[2359296];     // x  transposed [n][64] f16
__device__ float    g_y1t32[2359296];    // y1 [n][64] fp32
__device__ uint16_t g_y1t16[2359296];    // y1 [n][64] f16
__device__ float    g_y2t32[18874368];   // y2 [n][512] fp32
__device__ uint16_t g_y2t16[18874368];   // y2 [n][512] f16
__device__ float4   g_w4[331776];        // bilinear corner weights per (b,k,pix)
__device__ int4     g_o4[331776];        // corner offsets ((cy*W+cx)*C)

// ---------------- PTX helpers (generic compute_103-legal only) ---------------
__device__ __forceinline__ uint32_t smem_u32(const void* p) {
    uint32_t a;
    asm("{ .reg .u64 t; cvta.to.shared.u64 t, %1; cvt.u32.u64 %0, t; }"
        : "=r"(a) : "l"(p));
    return a;
}

__device__ __forceinline__ void cp16(uint32_t saddr, const void* g) {
    asm volatile("cp.async.cg.shared.global [%0], [%1], 16;"
                 :: "r"(saddr), "l"(g) : "memory");
}

// cp.async with runtime src-size: bytes beyond src_sz are zero-filled.
__device__ __forceinline__ void cp16z(uint32_t saddr, const void* g, uint32_t src_sz) {
    asm volatile("cp.async.cg.shared.global [%0], [%1], 16, %2;"
                 :: "r"(saddr), "l"(g), "r"(src_sz) : "memory");
}

__device__ __forceinline__ void cp_commit() {
    asm volatile("cp.async.commit_group;" ::: "memory");
}

template<int N>
__device__ __forceinline__ void cp_wait() {
    asm volatile("cp.async.wait_group %0;" :: "n"(N) : "memory");
}

__device__ __forceinline__ void ldsm4(uint32_t* r, uint32_t addr) {
    asm volatile("ldmatrix.sync.aligned.m8n8.x4.shared.b16 {%0,%1,%2,%3}, [%4];"
                 : "=r"(r[0]), "=r"(r[1]), "=r"(r[2]), "=r"(r[3]) : "r"(addr));
}

__device__ __forceinline__ void mma_f16(float* d, const uint32_t* a,
                                        const uint32_t* b) {
    asm volatile(
        "mma.sync.aligned.m16n8k16.row.col.f32.f16.f16.f32 "
        "{%0,%1,%2,%3}, {%4,%5,%6,%7}, {%8,%9}, {%0,%1,%2,%3};"
        : "+f"(d[0]), "+f"(d[1]), "+f"(d[2]), "+f"(d[3])
        : "r"(a[0]), "r"(a[1]), "r"(a[2]), "r"(a[3]), "r"(b[0]), "r"(b[1]));
}

// ---------------- 0) transpose x: [b][c][hw] fp32 -> [n][c] fp32+f16 ---------
__global__ void __launch_bounds__(256)
transpose_x_kernel(const float* __restrict__ x)
{
    __shared__ float s[32][33];
    const int tid = threadIdx.x;
    const int tx = tid & 31, ty = tid >> 5;
    const int hw0 = blockIdx.x * 32;
    const int c0  = blockIdx.y * 32;
    const int b   = blockIdx.z;
#pragma unroll
    for (int j = 0; j < 4; j++)
        s[ty + 8 * j][tx] = x[((size_t)b * 64 + c0 + ty + 8 * j) * HWc + hw0 + tx];
    __syncthreads();
#pragma unroll
    for (int j = 0; j < 4; j++) {
        float v = s[tx][ty + 8 * j];
        size_t n = (size_t)b * HWc + hw0 + ty + 8 * j;
        g_xt32[n * 64 + c0 + tx] = v;
        g_xt16[n * 64 + c0 + tx] = __half_as_ushort(__float2half_rn(v));
    }
}

// ---------------- 1) offset GEMM with implicit plain-im2col B ----------------
// om[27][N] = owA · B^T where B[n][tap*C+c] = y16[shift(n,tap)][c] (zero-pad).
// CTA tile 32(M) x 256(N), 8 warps (1M x 8N).
// Epilogue computes bilinear corner weights + offsets directly.
#define KC 64
#define RS 144
#define OASZ (32 * RS)
#define OSTG ((32 + 256) * RS)        // 41472 B
#define OSMEM_TOTAL (2 * OSTG)        // 82944 B

__global__ void __launch_bounds__(256, 2)
off_gemm_kernel(const float* __restrict__ bias,
                const uint16_t* __restrict__ y16, int C)
{
    extern __shared__ char smem[];
    const uint32_t sb = smem_u32(smem);
    const int tid = threadIdx.x, lid = tid & 31, wid = tid >> 5;
    const int warpN = wid;
    const int n0 = blockIdx.x * 256;
    const int K = 9 * C;
    const int cpt = C >> 6;           // chunks per tap

    float acc[2][4][4];
#pragma unroll
    for (int mt = 0; mt < 2; mt++)
#pragma unroll
        for (int nt = 0; nt < 4; nt++)
#pragma unroll
            for (int rg = 0; rg < 4; rg++) acc[mt][nt][rg] = 0.f;

    const char* pA = (const char*)g_wA;

    auto load_chunk = [&](int ch, int buf) {
        uint32_t sbase = sb + (uint32_t)buf * OSTG;
        int tap = ch / cpt;
        int coff = (ch - tap * cpt) * 64;
        int dr = tap / 3 - 1, dc = tap % 3 - 1;
#pragma unroll
        for (int i = 0; i < 9; i++) {
            int s   = tid + i * 256;
            int row = s >> 3;
            int seg = s & 7;
            if (row < 32) {
                const char* g = pA + (size_t)row * K * 2 + (size_t)ch * 128
                                + (size_t)seg * 16;
                cp16(sbase + row * RS + seg * 16, g);
            } else {
                int rt = row - 32;
                int n = n0 + rt;
                int b = n / HWc;
                int pix = n - b * HWc;
                int r = pix / WW, w = pix - r * WW;
                int rr = r + dr, cc = w + dc;
                bool v = (rr >= 0) & (rr < HH) & (cc >= 0) & (cc < WW);
                size_t src_n = (size_t)b * HWc + (v ? (rr * WW + cc) : 0);
                const char* g = (const char*)y16 + (src_n * C + coff) * 2
                                + (size_t)seg * 16;
                cp16z(sbase + OASZ + rt * RS + seg * 16, g, v ? 16u : 0u);
            }
        }
    };

    auto compute_chunk = [&](int buf) {
        uint32_t base = sb + (uint32_t)buf * OSTG;
        const uint32_t lrow = lid & 15;
        const uint32_t lcol = (lid >> 4) * 16;
#pragma unroll
        for (int ks = 0; ks < 4; ks++) {
            const uint32_t kb = ks * 32;
            uint32_t bb[4][2];
#pragma unroll
            for (int np = 0; np < 2; np++) {
                uint32_t t[4];
                uint32_t rr = warpN * 32 + np * 16 + lrow;
                ldsm4(t, base + OASZ + rr * RS + kb + lcol);
                bb[2 * np][0] = t[0]; bb[2 * np][1] = t[2];
                bb[2 * np + 1][0] = t[1]; bb[2 * np + 1][1] = t[3];
            }
            uint32_t af[2][4];
#pragma unroll
            for (int mt = 0; mt < 2; mt++) {
                uint32_t rr = mt * 16 + lrow;
                ldsm4(af[mt], base + rr * RS + kb + lcol);
            }
#pragma unroll
            for (int mt = 0; mt < 2; mt++)
#pragma unroll
                for (int nt = 0; nt < 4; nt++)
                    mma_f16(acc[mt][nt], af[mt], bb[nt]);
        }
    };

    const int nCh = K / KC;

    load_chunk(0, 0);
    cp_commit();

    for (int c = 0; c < nCh; c++) {
        int buf = c & 1;
        if (c + 1 < nCh) {
            load_chunk(c + 1, buf ^ 1);
            cp_commit();
            cp_wait<1>();
        } else {
            cp_wait<0>();
        }
        __syncthreads();
        compute_chunk(buf);
        __syncthreads();
    }

    // ---- fused epilogue: stage om tile, compute corner weights/offsets ------
    float* s_om = (float*)smem;          // [27][264]
    const int grp = lid >> 2;
    const int tig = lid & 3;
#pragma unroll
    for (int mt = 0; mt < 2; mt++) {
        int oA = mt * 16 + grp;
        int oB = oA + 8;
#pragma unroll
        for (int nt = 0; nt < 4; nt++) {
            int cn = warpN * 32 + nt * 8 + tig * 2;
            if (oA < 27) {
                float bv = bias[oA];
                s_om[oA * 264 + cn]     = acc[mt][nt][0] + bv;
                s_om[oA * 264 + cn + 1] = acc[mt][nt][1] + bv;
            }
            if (oB < 27) {
                float bv = bias[oB];
                s_om[oB * 264 + cn]     = acc[mt][nt][2] + bv;
                s_om[oB * 264 + cn + 1] = acc[mt][nt][3] + bv;
            }
        }
    }
    __syncthreads();

    {
        int n = n0 + tid;
        int b = n / HWc;
        int pix = n - b * HWc;
        int r = pix / WW, w = pix - r * WW;
#pragma unroll
        for (int k = 0; k < 9; k++) {
            float oy = s_om[(2 * k) * 264 + tid];
            float ox = s_om[(2 * k + 1) * 264 + tid];
            float mm = 1.f / (1.f + __expf(-s_om[(18 + k) * 264 + tid]));
            float pyv = (float)(r + k / 3 - 1) + oy;
            float pxv = (float)(w + k % 3 - 1) + ox;
            float y0f = floorf(pyv), x0f = floorf(pxv);
            float wy = pyv - y0f, wx = pxv - x0f;
            int y0 = (int)y0f, x0 = (int)x0f;
            int y1 = y0 + 1, x1 = x0 + 1;
            float vy0 = (y0 >= 0 && y0 < HH) ? 1.f : 0.f;
            float vy1 = (y1 >= 0 && y1 < HH) ? 1.f : 0.f;
            float vx0 = (x0 >= 0 && x0 < WW) ? 1.f : 0.f;
            float vx1 = (x1 >= 0 && x1 < WW) ? 1.f : 0.f;
            float4 wv;
            wv.x = (1.f - wy) * (1.f - wx) * mm * vy0 * vx0;
            wv.y = (1.f - wy) * wx         * mm * vy0 * vx1;
            wv.z = wy         * (1.f - wx) * mm * vy1 * vx0;
            wv.w = wy         * wx         * mm * vy1 * vx1;
            int cy0 = min(max(y0, 0), HH - 1), cy1 = min(max(y1, 0), HH - 1);
            int cx0 = min(max(x0, 0), WW - 1), cx1 = min(max(x1, 0), WW - 1);
            int4 ov;
            ov.x = (cy0 * WW + cx0) * C;
            ov.y = (cy0 * WW + cx1) * C;
            ov.z = (cy1 * WW + cx0) * C;
            ov.w = (cy1 * WW + cx1) * C;
            int idx = (b * 9 + k) * HWc + pix;
            g_w4[idx] = wv;
            g_o4[idx] = ov;
        }
    }
}

// ---------------- 2) deformable gather (streaming) -> g_col [n][K] f16 -------
// Warp owns one n; per tap: 2 broadcast loads of precomputed weights/offsets,
// then lanes stream contiguous c from y32 [n][c].
__global__ void __launch_bounds__(256)
gather_kernel(const float* __restrict__ y32, int C)
{
    const int lane = threadIdx.x & 31;
    const int wid  = threadIdx.x >> 5;
    const int n = blockIdx.x * 8 + wid;
    const int b = n / HWc;
    const int pix = n - b * HWc;
    const int K = 9 * C;

    const float* base = y32 + (size_t)b * HWc * C;
    const size_t outB = (size_t)n * K;

#pragma unroll
    for (int k = 0; k < 9; k++) {
        int idx = (b * 9 + k) * HWc + pix;
        float4 wv = g_w4[idx];
        int4   ov = g_o4[idx];
        const float* p00 = base + ov.x;
        const float* p01 = base + ov.y;
        const float* p10 = base + ov.z;
        const float* p11 = base + ov.w;

        for (int cb = 0; cb < C; cb += 64) {
            int c = cb + 2 * lane;
            float2 v00 = *(const float2*)(p00 + c);
            float2 v01 = *(const float2*)(p01 + c);
            float2 v10 = *(const float2*)(p10 + c);
            float2 v11 = *(const float2*)(p11 + c);
            float a = wv.x * v00.x + wv.y * v01.x + wv.z * v10.x + wv.w * v11.x;
            float d = wv.x * v00.y + wv.y * v01.y + wv.z * v10.y + wv.w * v11.y;
            uint32_t pk = (uint32_t)__half_as_ushort(__float2half_rn(a)) |
                          ((uint32_t)__half_as_ushort(__float2half_rn(d)) << 16);
            *reinterpret_cast<uint32_t*>(&g_col[outB + (size_t)k * C + c]) = pk;
        }
    }
}

// ---------------- 3a) weight repack: wA[o][tap*C+c] = f16(w[o][c][tap]) ------
__global__ void repack_kernel(const float* __restrict__ w,
                              int O, int Opad, int C)
{
    int K = 9 * C;
    int idx = blockIdx.x * blockDim.x + threadIdx.x;
    if (idx >= Opad * K) return;
    int kk = idx % K;
    int o  = idx / K;
    int tap = kk / C;
    int c   = kk % C;
    float v = (o < O) ? w[((size_t)o * C + c) * 9 + tap] : 0.f;
    g_wA[idx] = __half_as_ushort(__float2half_rn(v));
}

// ---------------- 3b) main fp16 HMMA GEMM, 2-stage, 2 CTAs/SM ----------------
// MODE 0: out = fp32 [b][O][hw] (harness).  MODE 1: y32 [n][O] + y16 [n][O].
#define ASZ (128 * RS)           // 18432 B
#define STG (2 * ASZ)            // 36864 B
#define GSMEM_TOTAL (2 * STG)    // 73728 B

template<int MODE>
__global__ void __launch_bounds__(256, 2)
dcn_gemm_kernel(const float* __restrict__ bias, float* __restrict__ out,
                uint16_t* __restrict__ out16, int K, int O)
{
    extern __shared__ char smem[];
    const uint32_t sb = smem_u32(smem);
    const int tid = threadIdx.x, lid = tid & 31, wid = tid >> 5;
    const int warpM = wid & 3;
    const int warpN = wid >> 2;
    const int m0 = blockIdx.x * 128;  // M fast -> B-tile L2 reuse
    const int n0 = blockIdx.y * 128;

    float acc[2][8][4];
#pragma unroll
    for (int mt = 0; mt < 2; mt++)
#pragma unroll
        for (int nt = 0; nt < 8; nt++)
#pragma unroll
            for (int rg = 0; rg < 4; rg++) acc[mt][nt][rg] = 0.f;

    const char* pA = (const char*)g_wA  + (size_t)m0 * K * 2;
    const char* pB = (const char*)g_col + (size_t)n0 * K * 2;

    auto load_chunk = [&](int c, int buf) {
        size_t kb = (size_t)c * (KC * 2);
        uint32_t sbase = sb + (uint32_t)buf * STG;
#pragma unroll
        for (int i = 0; i < 8; i++) {
            int s   = tid + i * 256;
            int row = s >> 3;
            int seg = s & 7;
            const char* g;
            uint32_t so;
            if (row < 128) {
                g  = pA + (size_t)row * K * 2 + kb + (size_t)seg * 16;
                so = sbase + row * RS + seg * 16;
            } else {
                int rr = row - 128;
                g  = pB + (size_t)rr * K * 2 + kb + (size_t)seg * 16;
                so = sbase + ASZ + rr * RS + seg * 16;
            }
            cp16(so, g);
        }
    };

    auto compute_chunk = [&](int buf) {
        uint32_t base = sb + (uint32_t)buf * STG;
        const uint32_t lrow = lid & 15;
        const uint32_t lcol = (lid >> 4) * 16;
#pragma unroll
        for (int ks = 0; ks < 4; ks++) {
            const uint32_t kb = ks * 32;
            uint32_t bb[8][2];
#pragma unroll
            for (int np = 0; np < 4; np++) {
                uint32_t t[4];
                uint32_t rr = warpN * 64 + np * 16 + lrow;
                ldsm4(t, base + ASZ + rr * RS + kb + lcol);
                bb[2 * np][0] = t[0]; bb[2 * np][1] = t[2];
                bb[2 * np + 1][0] = t[1]; bb[2 * np + 1][1] = t[3];
            }
            uint32_t af[2][4];
#pragma unroll
            for (int mt = 0; mt < 2; mt++) {
                uint32_t rr = warpM * 32 + mt * 16 + lrow;
                ldsm4(af[mt], base + rr * RS + kb + lcol);
            }
#pragma unroll
            for (int mt = 0; mt < 2; mt++)
#pragma unroll
                for (int nt = 0; nt < 8; nt++)
                    mma_f16(acc[mt][nt], af[mt], bb[nt]);
        }
    };

    const int nCh = K / KC;

    load_chunk(0, 0);
    cp_commit();

    for (int c = 0; c < nCh; c++) {
        int buf = c & 1;
        if (c + 1 < nCh) {
            load_chunk(c + 1, buf ^ 1);
            cp_commit();
            cp_wait<1>();
        } else {
            cp_wait<0>();
        }
        __syncthreads();
        compute_chunk(buf);
        __syncthreads();
    }

    const int grp = lid >> 2;
    const int tig = lid & 3;

    if (MODE == 0) {
        const int b   = n0 / HWc;
        const int hw0 = n0 % HWc;
#pragma unroll
        for (int mt = 0; mt < 2; mt++) {
            int oA = m0 + warpM * 32 + mt * 16 + grp;
            int oB = oA + 8;
#pragma unroll
            for (int nt = 0; nt < 8; nt++) {
                int cn = warpN * 64 + nt * 8 + tig * 2;
                if (oA < O) {
                    float bv = bias[oA];
                    float2 v = make_float2(acc[mt][nt][0] + bv, acc[mt][nt][1] + bv);
                    *(float2*)(out + ((size_t)b * O + oA) * HWc + hw0 + cn) = v;
                }
                if (oB < O) {
                    float bv = bias[oB];
                    float2 v = make_float2(acc[mt][nt][2] + bv, acc[mt][nt][3] + bv);
                    *(float2*)(out + ((size_t)b * O + oB) * HWc + hw0 + cn) = v;
                }
            }
        }
    } else {
        // stage [n_local][o_local] fp32 tile in smem, then coalesced [n][c] writes
        float* s32 = (float*)smem;       // pitch 132
        __syncthreads();                 // all ldsm on smem done
#pragma unroll
        for (int mt = 0; mt < 2; mt++) {
            int oAl = warpM * 32 + mt * 16 + grp;
            int oBl = oAl + 8;
            float bvA = (m0 + oAl < O) ? bias[m0 + oAl] : 0.f;
            float bvB = (m0 + oBl < O) ? bias[m0 + oBl] : 0.f;
#pragma unroll
            for (int nt = 0; nt < 8; nt++) {
                int cn = warpN * 64 + nt * 8 + tig * 2;
                s32[(size_t)cn * 132 + oAl]       = acc[mt][nt][0] + bvA;
                s32[(size_t)(cn + 1) * 132 + oAl] = acc[mt][nt][1] + bvA;
                s32[(size_t)cn * 132 + oBl]       = acc[mt][nt][2] + bvB;
                s32[(size_t)(cn + 1) * 132 + oBl] = acc[mt][nt][3] + bvB;
            }
        }
        __syncthreads();
        const int row  = tid >> 1;          // 0..127 (n local)
        const int half = tid & 1;           // 0..1 (64 cols each)
        const size_t n = (size_t)(n0 + row);
#pragma unroll
        for (int j = 0; j < 16; j++) {
            int col = half * 64 + j * 4;
            int o = m0 + col;
            if (o < O) {
                float4 v = *(float4*)(s32 + (size_t)row * 132 + col);
                *(float4*)(out + n * O + o) = v;
                __half2 h0 = __floats2half2_rn(v.x, v.y);
                __half2 h1 = __floats2half2_rn(v.z, v.w);
                uint2 pk;
                pk.x = *(uint32_t*)&h0;
                pk.y = *(uint32_t*)&h1;
                *(uint2*)(out16 + n * O + o) = pk;
            }
        }
    }
}

// ---------------- host-side layer driver -------------------------------------
static void run_layer(const float* in32, const uint16_t* in16, int C,
                      const float* ow, const float* obias,
                      const float* w, const float* bias,
                      int O, int Opad, int mode, float* out, uint16_t* out16)
{
    int K = 9 * C;

    // offset path: implicit-im2col GEMM -> corner weights/offsets (fused)
    repack_kernel<<<(32 * K + 255) / 256, 256>>>(ow, 27, 32, C);
    off_gemm_kernel<<<NN / 256, 256, OSMEM_TOTAL>>>(obias, in16, C);

    // main path: streaming deformable gather -> main GEMM
    gather_kernel<<<NN / 8, 256>>>(in32, C);
    repack_kernel<<<(Opad * K + 255) / 256, 256>>>(w, O, Opad, C);

    dim3 grid(Opad / 128, NN / 128);
    if (mode == 0)
        dcn_gemm_kernel<0><<<grid, 256, GSMEM_TOTAL>>>(bias, out, out16, K, O);
    else
        dcn_gemm_kernel<1><<<grid, 256, GSMEM_TOTAL>>>(bias, out, out16, K, O);
}

extern "C" void kernel_launch(void* const* d_in, const int* in_sizes, int n_in,
                              void* d_out, int out_size)
{
    const float* x   = (const float*)d_in[0];
    const float* ow1 = (const float*)d_in[1];
    const float* ob1 = (const float*)d_in[2];
    const float* w1  = (const float*)d_in[3];
    const float* b1  = (const float*)d_in[4];
    const float* ow2 = (const float*)d_in[5];
    const float* ob2 = (const float*)d_in[6];
    const float* w2  = (const float*)d_in[7];
    const float* b2  = (const float*)d_in[8];
    const float* ow3 = (const float*)d_in[9];
    const float* ob3 = (const float*)d_in[10];
    const float* w3  = (const float*)d_in[11];
    const float* b3  = (const float*)d_in[12];
    float* out = (float*)d_out;

    cudaFuncSetAttribute(dcn_gemm_kernel<0>,
                         cudaFuncAttributeMaxDynamicSharedMemorySize, GSMEM_TOTAL);
    cudaFuncSetAttribute(dcn_gemm_kernel<1>,
                         cudaFuncAttributeMaxDynamicSharedMemorySize, GSMEM_TOTAL);
    cudaFuncSetAttribute(off_gemm_kernel,
                         cudaFuncAttributeMaxDynamicSharedMemorySize, OSMEM_TOTAL);

    float *xt32, *y1t32, *y2t32;
    uint16_t *xt16, *y1t16, *y2t16;
    cudaGetSymbolAddress((void**)&xt32,  g_xt32);
    cudaGetSymbolAddress((void**)&xt16,  g_xt16);
    cudaGetSymbolAddress((void**)&y1t32, g_y1t32);
    cudaGetSymbolAddress((void**)&y1t16, g_y1t16);
    cudaGetSymbolAddress((void**)&y2t32, g_y2t32);
    cudaGetSymbolAddress((void**)&y2t16, g_y2t16);

    dim3 gT(HWc / 32, 2, BB);
    transpose_x_kernel<<<gT, 256>>>(x);

    run_layer(xt32,  xt16,  64,  ow1, ob1, w1, b1,  64, 128, 1, y1t32, y1t16);
    run_layer(y1t32, y1t16, 64,  ow2, ob2, w2, b2, 512, 512, 1, y2t32, y2t16);
    run_layer(y2t32, y2t16, 512, ow3, ob3, w3, b3, 256, 256, 0, out, nullptr);
}

// round 17
// speedup vs baseline: 3.0470x; 1.0317x over previous
#include <cuda_runtime.h>
#include <cuda_fp16.h>
#include <math.h>
#include <stdint.h>

#define HH 96
#define WW 96
#define HWc 9216         // 96*96
#define BB 4
#define NN 36864         // BB*HWc

// ---------------- scratch (static device arrays; no cudaMalloc) --------------
__device__ uint16_t g_col[169869312];    // f16: deformable im2col [NN][K]
__device__ uint16_t g_wA[1179648];       // f16: [Opad][K] K-major (shared)
__device__ float    g_xt32[2359296];     // x  transposed [n][64] fp32
__device__ uint16_t g_xt16[2359296];     // x  transposed [n][64] f16
__device__ float    g_y1t32[2359296];    // y1 [n][64] fp32
__device__ uint16_t g_y1t16[2359296];    // y1 [n][64] f16
__device__ float    g_y2t32[18874368];   // y2 [n][512] fp32
__device__ uint16_t g_y2t16[18874368];   // y2 [n][512] f16
__device__ float4   g_w4[331776];        // bilinear corner weights per (b,k,pix)
__device__ int4     g_o4[331776];        // corner offsets ((cy*W+cx)*C)

// ---------------- PTX helpers (generic compute_103-legal only) ---------------
__device__ __forceinline__ uint32_t smem_u32(const void* p) {
    uint32_t a;
    asm("{ .reg .u64 t; cvta.to.shared.u64 t, %1; cvt.u32.u64 %0, t; }"
        : "=r"(a) : "l"(p));
    return a;
}

__device__ __forceinline__ void cp16(uint32_t saddr, const void* g) {
    asm volatile("cp.async.cg.shared.global [%0], [%1], 16;"
                 :: "r"(saddr), "l"(g) : "memory");
}

// cp.async with runtime src-size: bytes beyond src_sz are zero-filled.
__device__ __forceinline__ void cp16z(uint32_t saddr, const void* g, uint32_t src_sz) {
    asm volatile("cp.async.cg.shared.global [%0], [%1], 16, %2;"
                 :: "r"(saddr), "l"(g), "r"(src_sz) : "memory");
}

__device__ __forceinline__ void cp_commit() {
    asm volatile("cp.async.commit_group;" ::: "memory");
}

template<int N>
__device__ __forceinline__ void cp_wait() {
    asm volatile("cp.async.wait_group %0;" :: "n"(N) : "memory");
}

__device__ __forceinline__ void ldsm4(uint32_t* r, uint32_t addr) {
    asm volatile("ldmatrix.sync.aligned.m8n8.x4.shared.b16 {%0,%1,%2,%3}, [%4];"
                 : "=r"(r[0]), "=r"(r[1]), "=r"(r[2]), "=r"(r[3]) : "r"(addr));
}

__device__ __forceinline__ void mma_f16(float* d, const uint32_t* a,
                                        const uint32_t* b) {
    asm volatile(
        "mma.sync.aligned.m16n8k16.row.col.f32.f16.f16.f32 "
        "{%0,%1,%2,%3}, {%4,%5,%6,%7}, {%8,%9}, {%0,%1,%2,%3};"
        : "+f"(d[0]), "+f"(d[1]), "+f"(d[2]), "+f"(d[3])
        : "r"(a[0]), "r"(a[1]), "r"(a[2]), "r"(a[3]), "r"(b[0]), "r"(b[1]));
}

// ---------------- 0) transpose x: [b][c][hw] fp32 -> [n][c] fp32+f16 ---------
__global__ void __launch_bounds__(256)
transpose_x_kernel(const float* __restrict__ x)
{
    __shared__ float s[32][33];
    const int tid = threadIdx.x;
    const int tx = tid & 31, ty = tid >> 5;
    const int hw0 = blockIdx.x * 32;
    const int c0  = blockIdx.y * 32;
    const int b   = blockIdx.z;
#pragma unroll
    for (int j = 0; j < 4; j++)
        s[ty + 8 * j][tx] = x[((size_t)b * 64 + c0 + ty + 8 * j) * HWc + hw0 + tx];
    __syncthreads();
#pragma unroll
    for (int j = 0; j < 4; j++) {
        float v = s[tx][ty + 8 * j];
        size_t n = (size_t)b * HWc + hw0 + ty + 8 * j;
        g_xt32[n * 64 + c0 + tx] = v;
        g_xt16[n * 64 + c0 + tx] = __half_as_ushort(__float2half_rn(v));
    }
}

// ---------------- 1) offset GEMM with implicit plain-im2col B ----------------
// om[27][N] = owA · B^T where B[n][tap*C+c] = y16[shift(n,tap)][c] (zero-pad).
// CTA tile 32(M) x 256(N), 8 warps (1M x 8N).
// Epilogue computes bilinear corner weights + offsets directly.
#define KC 64
#define RS 144
#define OASZ (32 * RS)
#define OSTG ((32 + 256) * RS)        // 41472 B
#define OSMEM_TOTAL (2 * OSTG)        // 82944 B

__global__ void __launch_bounds__(256, 2)
off_gemm_kernel(const float* __restrict__ bias,
                const uint16_t* __restrict__ y16, int C)
{
    extern __shared__ char smem[];
    const uint32_t sb = smem_u32(smem);
    const int tid = threadIdx.x, lid = tid & 31, wid = tid >> 5;
    const int warpN = wid;
    const int n0 = blockIdx.x * 256;
    const int K = 9 * C;
    const int cpt = C >> 6;           // chunks per tap

    float acc[2][4][4];
#pragma unroll
    for (int mt = 0; mt < 2; mt++)
#pragma unroll
        for (int nt = 0; nt < 4; nt++)
#pragma unroll
            for (int rg = 0; rg < 4; rg++) acc[mt][nt][rg] = 0.f;

    const char* pA = (const char*)g_wA;

    auto load_chunk = [&](int ch, int buf) {
        uint32_t sbase = sb + (uint32_t)buf * OSTG;
        int tap = ch / cpt;
        int coff = (ch - tap * cpt) * 64;
        int dr = tap / 3 - 1, dc = tap % 3 - 1;
#pragma unroll
        for (int i = 0; i < 9; i++) {
            int s   = tid + i * 256;
            int row = s >> 3;
            int seg = s & 7;
            if (row < 32) {
                const char* g = pA + (size_t)row * K * 2 + (size_t)ch * 128
                                + (size_t)seg * 16;
                cp16(sbase + row * RS + seg * 16, g);
            } else {
                int rt = row - 32;
                int n = n0 + rt;
                int b = n / HWc;
                int pix = n - b * HWc;
                int r = pix / WW, w = pix - r * WW;
                int rr = r + dr, cc = w + dc;
                bool v = (rr >= 0) & (rr < HH) & (cc >= 0) & (cc < WW);
                size_t src_n = (size_t)b * HWc + (v ? (rr * WW + cc) : 0);
                const char* g = (const char*)y16 + (src_n * C + coff) * 2
                                + (size_t)seg * 16;
                cp16z(sbase + OASZ + rt * RS + seg * 16, g, v ? 16u : 0u);
            }
        }
    };

    auto compute_chunk = [&](int buf) {
        uint32_t base = sb + (uint32_t)buf * OSTG;
        const uint32_t lrow = lid & 15;
        const uint32_t lcol = (lid >> 4) * 16;
#pragma unroll
        for (int ks = 0; ks < 4; ks++) {
            const uint32_t kb = ks * 32;
            uint32_t bb[4][2];
#pragma unroll
            for (int np = 0; np < 2; np++) {
                uint32_t t[4];
                uint32_t rr = warpN * 32 + np * 16 + lrow;
                ldsm4(t, base + OASZ + rr * RS + kb + lcol);
                bb[2 * np][0] = t[0]; bb[2 * np][1] = t[2];
                bb[2 * np + 1][0] = t[1]; bb[2 * np + 1][1] = t[3];
            }
            uint32_t af[2][4];
#pragma unroll
            for (int mt = 0; mt < 2; mt++) {
                uint32_t rr = mt * 16 + lrow;
                ldsm4(af[mt], base + rr * RS + kb + lcol);
            }
#pragma unroll
            for (int mt = 0; mt < 2; mt++)
#pragma unroll
                for (int nt = 0; nt < 4; nt++)
                    mma_f16(acc[mt][nt], af[mt], bb[nt]);
        }
    };

    const int nCh = K / KC;

    load_chunk(0, 0);
    cp_commit();

    for (int c = 0; c < nCh; c++) {
        int buf = c & 1;
        if (c + 1 < nCh) {
            load_chunk(c + 1, buf ^ 1);
            cp_commit();
            cp_wait<1>();
        } else {
            cp_wait<0>();
        }
        __syncthreads();
        compute_chunk(buf);
        __syncthreads();
    }

    // ---- fused epilogue: stage om tile, compute corner weights/offsets ------
    float* s_om = (float*)smem;          // [27][264]
    const int grp = lid >> 2;
    const int tig = lid & 3;
#pragma unroll
    for (int mt = 0; mt < 2; mt++) {
        int oA = mt * 16 + grp;
        int oB = oA + 8;
#pragma unroll
        for (int nt = 0; nt < 4; nt++) {
            int cn = warpN * 32 + nt * 8 + tig * 2;
            if (oA < 27) {
                float bv = bias[oA];
                s_om[oA * 264 + cn]     = acc[mt][nt][0] + bv;
                s_om[oA * 264 + cn + 1] = acc[mt][nt][1] + bv;
            }
            if (oB < 27) {
                float bv = bias[oB];
                s_om[oB * 264 + cn]     = acc[mt][nt][2] + bv;
                s_om[oB * 264 + cn + 1] = acc[mt][nt][3] + bv;
            }
        }
    }
    __syncthreads();

    {
        int n = n0 + tid;
        int b = n / HWc;
        int pix = n - b * HWc;
        int r = pix / WW, w = pix - r * WW;
#pragma unroll
        for (int k = 0; k < 9; k++) {
            float oy = s_om[(2 * k) * 264 + tid];
            float ox = s_om[(2 * k + 1) * 264 + tid];
            float mm = 1.f / (1.f + __expf(-s_om[(18 + k) * 264 + tid]));
            float pyv = (float)(r + k / 3 - 1) + oy;
            float pxv = (float)(w + k % 3 - 1) + ox;
            float y0f = floorf(pyv), x0f = floorf(pxv);
            float wy = pyv - y0f, wx = pxv - x0f;
            int y0 = (int)y0f, x0 = (int)x0f;
            int y1 = y0 + 1, x1 = x0 + 1;
            float vy0 = (y0 >= 0 && y0 < HH) ? 1.f : 0.f;
            float vy1 = (y1 >= 0 && y1 < HH) ? 1.f : 0.f;
            float vx0 = (x0 >= 0 && x0 < WW) ? 1.f : 0.f;
            float vx1 = (x1 >= 0 && x1 < WW) ? 1.f : 0.f;
            float4 wv;
            wv.x = (1.f - wy) * (1.f - wx) * mm * vy0 * vx0;
            wv.y = (1.f - wy) * wx         * mm * vy0 * vx1;
            wv.z = wy         * (1.f - wx) * mm * vy1 * vx0;
            wv.w = wy         * wx         * mm * vy1 * vx1;
            int cy0 = min(max(y0, 0), HH - 1), cy1 = min(max(y1, 0), HH - 1);
            int cx0 = min(max(x0, 0), WW - 1), cx1 = min(max(x1, 0), WW - 1);
            int4 ov;
            ov.x = (cy0 * WW + cx0) * C;
            ov.y = (cy0 * WW + cx1) * C;
            ov.z = (cy1 * WW + cx0) * C;
            ov.w = (cy1 * WW + cx1) * C;
            int idx = (b * 9 + k) * HWc + pix;
            g_w4[idx] = wv;
            g_o4[idx] = ov;
        }
    }
}

// ---------------- 2) deformable gather (streaming, high-ILP) -----------------
// Warp owns one n. All 9 taps' weights/offsets prefetched; corner loads are
// issued in groups (12-16 in flight) to cover load latency.
template<int C>
__global__ void __launch_bounds__(256)
gather_kernel(const float* __restrict__ y32)
{
    const int lane = threadIdx.x & 31;
    const int wid  = threadIdx.x >> 5;
    const int n = blockIdx.x * 8 + wid;
    const int b = n / HWc;
    const int pix = n - b * HWc;
    const int K = 9 * C;

    const float* base = y32 + (size_t)b * HWc * C;
    const size_t outB = (size_t)n * K;

    float4 wv[9];
    int4   ov[9];
#pragma unroll
    for (int k = 0; k < 9; k++) {
        int idx = (b * 9 + k) * HWc + pix;
        wv[k] = g_w4[idx];
        ov[k] = g_o4[idx];
    }

    if (C == 64) {
        // 3 groups of 3 taps; 12 float2 loads in flight per group
#pragma unroll
        for (int g = 0; g < 3; g++) {
            float2 v[3][4];
#pragma unroll
            for (int j = 0; j < 3; j++) {
                int k = g * 3 + j;
                int c = 2 * lane;
                v[j][0] = *(const float2*)(base + ov[k].x + c);
                v[j][1] = *(const float2*)(base + ov[k].y + c);
                v[j][2] = *(const float2*)(base + ov[k].z + c);
                v[j][3] = *(const float2*)(base + ov[k].w + c);
            }
#pragma unroll
            for (int j = 0; j < 3; j++) {
                int k = g * 3 + j;
                int c = 2 * lane;
                float a = wv[k].x * v[j][0].x + wv[k].y * v[j][1].x
                        + wv[k].z * v[j][2].x + wv[k].w * v[j][3].x;
                float d = wv[k].x * v[j][0].y + wv[k].y * v[j][1].y
                        + wv[k].z * v[j][2].y + wv[k].w * v[j][3].y;
                uint32_t pk = (uint32_t)__half_as_ushort(__float2half_rn(a)) |
                              ((uint32_t)__half_as_ushort(__float2half_rn(d)) << 16);
                *reinterpret_cast<uint32_t*>(&g_col[outB + (size_t)k * C + c]) = pk;
            }
        }
    } else {
#pragma unroll
        for (int k = 0; k < 9; k++) {
            const float* p00 = base + ov[k].x;
            const float* p01 = base + ov[k].y;
            const float* p10 = base + ov[k].z;
            const float* p11 = base + ov[k].w;
#pragma unroll
            for (int gb = 0; gb < C / 256; gb++) {
                float2 v[4][4];
#pragma unroll
                for (int j = 0; j < 4; j++) {
                    int c = gb * 256 + j * 64 + 2 * lane;
                    v[j][0] = *(const float2*)(p00 + c);
                    v[j][1] = *(const float2*)(p01 + c);
                    v[j][2] = *(const float2*)(p10 + c);
                    v[j][3] = *(const float2*)(p11 + c);
                }
#pragma unroll
                for (int j = 0; j < 4; j++) {
                    int c = gb * 256 + j * 64 + 2 * lane;
                    float a = wv[k].x * v[j][0].x + wv[k].y * v[j][1].x
                            + wv[k].z * v[j][2].x + wv[k].w * v[j][3].x;
                    float d = wv[k].x * v[j][0].y + wv[k].y * v[j][1].y
                            + wv[k].z * v[j][2].y + wv[k].w * v[j][3].y;
                    uint32_t pk = (uint32_t)__half_as_ushort(__float2half_rn(a)) |
                                  ((uint32_t)__half_as_ushort(__float2half_rn(d)) << 16);
                    *reinterpret_cast<uint32_t*>(&g_col[outB + (size_t)k * C + c]) = pk;
                }
            }
        }
    }
}

// ---------------- 3a) weight repack: wA[o][tap*C+c] = f16(w[o][c][tap]) ------
__global__ void repack_kernel(const float* __restrict__ w,
                              int O, int Opad, int C)
{
    int K = 9 * C;
    int idx = blockIdx.x * blockDim.x + threadIdx.x;
    if (idx >= Opad * K) return;
    int kk = idx % K;
    int o  = idx / K;
    int tap = kk / C;
    int c   = kk % C;
    float v = (o < O) ? w[((size_t)o * C + c) * 9 + tap] : 0.f;
    g_wA[idx] = __half_as_ushort(__float2half_rn(v));
}

// ---------------- 3b) main fp16 HMMA GEMM, 3-stage, 2 CTAs/SM ----------------
// MODE 0: out = fp32 [b][O][hw] (harness).  MODE 1: y32 [n][O] + y16 [n][O].
// 3-stage cp.async circular buffer, ONE __syncthreads per K-chunk.
#define ASZ (128 * RS)           // 18432 B
#define STG (2 * ASZ)            // 36864 B
#define GSMEM_TOTAL (3 * STG)    // 110592 B -> 2 CTAs/SM (221 KB of 228)

template<int MODE>
__global__ void __launch_bounds__(256, 2)
dcn_gemm_kernel(const float* __restrict__ bias, float* __restrict__ out,
                uint16_t* __restrict__ out16, int K, int O)
{
    extern __shared__ char smem[];
    const uint32_t sb = smem_u32(smem);
    const int tid = threadIdx.x, lid = tid & 31, wid = tid >> 5;
    const int warpM = wid & 3;
    const int warpN = wid >> 2;
    const int m0 = blockIdx.x * 128;  // M fast -> B-tile L2 reuse
    const int n0 = blockIdx.y * 128;

    float acc[2][8][4];
#pragma unroll
    for (int mt = 0; mt < 2; mt++)
#pragma unroll
        for (int nt = 0; nt < 8; nt++)
#pragma unroll
            for (int rg = 0; rg < 4; rg++) acc[mt][nt][rg] = 0.f;

    const char* pA = (const char*)g_wA  + (size_t)m0 * K * 2;
    const char* pB = (const char*)g_col + (size_t)n0 * K * 2;

    auto load_chunk = [&](int c, int buf) {
        size_t kb = (size_t)c * (KC * 2);
        uint32_t sbase = sb + (uint32_t)buf * STG;
#pragma unroll
        for (int i = 0; i < 8; i++) {
            int s   = tid + i * 256;
            int row = s >> 3;
            int seg = s & 7;
            const char* g;
            uint32_t so;
            if (row < 128) {
                g  = pA + (size_t)row * K * 2 + kb + (size_t)seg * 16;
                so = sbase + row * RS + seg * 16;
            } else {
                int rr = row - 128;
                g  = pB + (size_t)rr * K * 2 + kb + (size_t)seg * 16;
                so = sbase + ASZ + rr * RS + seg * 16;
            }
            cp16(so, g);
        }
    };

    auto compute_chunk = [&](int buf) {
        uint32_t base = sb + (uint32_t)buf * STG;
        const uint32_t lrow = lid & 15;
        const uint32_t lcol = (lid >> 4) * 16;
#pragma unroll
        for (int ks = 0; ks < 4; ks++) {
            const uint32_t kb = ks * 32;
            uint32_t bb[8][2];
#pragma unroll
            for (int np = 0; np < 4; np++) {
                uint32_t t[4];
                uint32_t rr = warpN * 64 + np * 16 + lrow;
                ldsm4(t, base + ASZ + rr * RS + kb + lcol);
                bb[2 * np][0] = t[0]; bb[2 * np][1] = t[2];
                bb[2 * np + 1][0] = t[1]; bb[2 * np + 1][1] = t[3];
            }
            uint32_t af[2][4];
#pragma unroll
            for (int mt = 0; mt < 2; mt++) {
                uint32_t rr = warpM * 32 + mt * 16 + lrow;
                ldsm4(af[mt], base + rr * RS + kb + lcol);
            }
#pragma unroll
            for (int mt = 0; mt < 2; mt++)
#pragma unroll
                for (int nt = 0; nt < 8; nt++)
                    mma_f16(acc[mt][nt], af[mt], bb[nt]);
        }
    };

    const int nCh = K / KC;   // >= 9 always

    load_chunk(0, 0); cp_commit();
    load_chunk(1, 1); cp_commit();

    int buf = 0;
    for (int c = 0; c < nCh; c++) {
        if (c + 1 < nCh) cp_wait<1>(); else cp_wait<0>();   // chunk c arrived
        __syncthreads();   // also retires compute(c-1) -> buffer (c+2)%3 free
        if (c + 2 < nCh) {
            int nb = buf + 2; if (nb >= 3) nb -= 3;
            load_chunk(c + 2, nb);
            cp_commit();
        }
        compute_chunk(buf);
        if (++buf == 3) buf = 0;
    }
    __syncthreads();

    const int grp = lid >> 2;
    const int tig = lid & 3;

    if (MODE == 0) {
        const int b   = n0 / HWc;
        const int hw0 = n0 % HWc;
#pragma unroll
        for (int mt = 0; mt < 2; mt++) {
            int oA = m0 + warpM * 32 + mt * 16 + grp;
            int oB = oA + 8;
#pragma unroll
            for (int nt = 0; nt < 8; nt++) {
                int cn = warpN * 64 + nt * 8 + tig * 2;
                if (oA < O) {
                    float bv = bias[oA];
                    float2 v = make_float2(acc[mt][nt][0] + bv, acc[mt][nt][1] + bv);
                    *(float2*)(out + ((size_t)b * O + oA) * HWc + hw0 + cn) = v;
                }
                if (oB < O) {
                    float bv = bias[oB];
                    float2 v = make_float2(acc[mt][nt][2] + bv, acc[mt][nt][3] + bv);
                    *(float2*)(out + ((size_t)b * O + oB) * HWc + hw0 + cn) = v;
                }
            }
        }
    } else {
        // stage [n_local][o_local] fp32 tile in smem, then coalesced [n][c] writes
        float* s32 = (float*)smem;       // pitch 132
#pragma unroll
        for (int mt = 0; mt < 2; mt++) {
            int oAl = warpM * 32 + mt * 16 + grp;
            int oBl = oAl + 8;
            float bvA = (m0 + oAl < O) ? bias[m0 + oAl] : 0.f;
            float bvB = (m0 + oBl < O) ? bias[m0 + oBl] : 0.f;
#pragma unroll
            for (int nt = 0; nt < 8; nt++) {
                int cn = warpN * 64 + nt * 8 + tig * 2;
                s32[(size_t)cn * 132 + oAl]       = acc[mt][nt][0] + bvA;
                s32[(size_t)(cn + 1) * 132 + oAl] = acc[mt][nt][1] + bvA;
                s32[(size_t)cn * 132 + oBl]       = acc[mt][nt][2] + bvB;
                s32[(size_t)(cn + 1) * 132 + oBl] = acc[mt][nt][3] + bvB;
            }
        }
        __syncthreads();
        const int row  = tid >> 1;          // 0..127 (n local)
        const int half = tid & 1;           // 0..1 (64 cols each)
        const size_t n = (size_t)(n0 + row);
#pragma unroll
        for (int j = 0; j < 16; j++) {
            int col = half * 64 + j * 4;
            int o = m0 + col;
            if (o < O) {
                float4 v = *(float4*)(s32 + (size_t)row * 132 + col);
                *(float4*)(out + n * O + o) = v;
                __half2 h0 = __floats2half2_rn(v.x, v.y);
                __half2 h1 = __floats2half2_rn(v.z, v.w);
                uint2 pk;
                pk.x = *(uint32_t*)&h0;
                pk.y = *(uint32_t*)&h1;
                *(uint2*)(out16 + n * O + o) = pk;
            }
        }
    }
}

// ---------------- host-side layer driver -------------------------------------
template<int C>
static void run_layer(const float* in32, const uint16_t* in16,
                      const float* ow, const float* obias,
                      const float* w, const float* bias,
                      int O, int Opad, int mode, float* out, uint16_t* out16)
{
    int K = 9 * C;

    // offset path: implicit-im2col GEMM -> corner weights/offsets (fused)
    repack_kernel<<<(32 * K + 255) / 256, 256>>>(ow, 27, 32, C);
    off_gemm_kernel<<<NN / 256, 256, OSMEM_TOTAL>>>(obias, in16, C);

    // main path: streaming deformable gather -> main GEMM
    gather_kernel<C><<<NN / 8, 256>>>(in32);
    repack_kernel<<<(Opad * K + 255) / 256, 256>>>(w, O, Opad, C);

    dim3 grid(Opad / 128, NN / 128);
    if (mode == 0)
        dcn_gemm_kernel<0><<<grid, 256, GSMEM_TOTAL>>>(bias, out, out16, K, O);
    else
        dcn_gemm_kernel<1><<<grid, 256, GSMEM_TOTAL>>>(bias, out, out16, K, O);
}

extern "C" void kernel_launch(void* const* d_in, const int* in_sizes, int n_in,
                              void* d_out, int out_size)
{
    const float* x   = (const float*)d_in[0];
    const float* ow1 = (const float*)d_in[1];
    const float* ob1 = (const float*)d_in[2];
    const float* w1  = (const float*)d_in[3];
    const float* b1  = (const float*)d_in[4];
    const float* ow2 = (const float*)d_in[5];
    const float* ob2 = (const float*)d_in[6];
    const float* w2  = (const float*)d_in[7];
    const float* b2  = (const float*)d_in[8];
    const float* ow3 = (const float*)d_in[9];
    const float* ob3 = (const float*)d_in[10];
    const float* w3  = (const float*)d_in[11];
    const float* b3  = (const float*)d_in[12];
    float* out = (float*)d_out;

    cudaFuncSetAttribute(dcn_gemm_kernel<0>,
                         cudaFuncAttributeMaxDynamicSharedMemorySize, GSMEM_TOTAL);
    cudaFuncSetAttribute(dcn_gemm_kernel<1>,
                         cudaFuncAttributeMaxDynamicSharedMemorySize, GSMEM_TOTAL);
    cudaFuncSetAttribute(off_gemm_kernel,
                         cudaFuncAttributeMaxDynamicSharedMemorySize, OSMEM_TOTAL);

    float *xt32, *y1t32, *y2t32;
    uint16_t *xt16, *y1t16, *y2t16;
    cudaGetSymbolAddress((void**)&xt32,  g_xt32);
    cudaGetSymbolAddress((void**)&xt16,  g_xt16);
    cudaGetSymbolAddress((void**)&y1t32, g_y1t32);
    cudaGetSymbolAddress((void**)&y1t16, g_y1t16);
    cudaGetSymbolAddress((void**)&y2t32, g_y2t32);
    cudaGetSymbolAddress((void**)&y2t16, g_y2t16);

    dim3 gT(HWc / 32, 2, BB);
    transpose_x_kernel<<<gT, 256>>>(x);

    run_layer<64> (xt32,  xt16,  ow1, ob1, w1, b1,  64, 128, 1, y1t32, y1t16);
    run_layer<64> (y1t32, y1t16, ow2, ob2, w2, b2, 512, 512, 1, y2t32, y2t16);
    run_layer<512>(y2t32, y2t16, ow3, ob3, w3, b3, 256, 256, 0, out, nullptr);
}